// round 1
// baseline (speedup 1.0000x reference)
#include <cuda_runtime.h>
#include <math.h>
#include <stdint.h>

// Problem constants
#define B_  64
#define L_  196
#define F_  512
#define T_  32
#define H_  512
#define D_  512
#define V_  32000
#define G4_ 2048               // 4*H
#define M_ENC (B_*L_)          // 12544
#define M_FC  (T_*B_)          // 2048
#define KS_ 8                  // K-splits for LSTM gates GEMM
#define KLEN_ ((D_+F_+H_)/KS_) // 1536/8 = 192

// ---------------- scratch (static device globals; no allocations) ----------
__device__ float g_encproj[M_ENC * H_];      // [B*L, H]
__device__ float g_emb[T_ * B_ * D_];        // [t, b, d]
__device__ float g_ctx[B_ * F_];             // current context
__device__ float g_h[B_ * H_];
__device__ float g_c[B_ * H_];
__device__ float g_dec[B_ * H_];
__device__ float g_Hall[T_ * B_ * H_];       // [(t*B+b), h]
__device__ float g_gpart[(size_t)KS_ * G4_ * B_]; // [s, gate, b]

// ---------------- init: zero h/c, gather embeddings ------------------------
__global__ void k_init(const int* __restrict__ captions,
                       const float* __restrict__ embedding) {
    int idx = blockIdx.x * 256 + threadIdx.x;      // 0 .. T*B*D-1 (exact grid)
    if (idx < B_ * H_) { g_h[idx] = 0.f; g_c[idx] = 0.f; }
    int t   = idx >> 15;          // / (B_*D_) = /32768
    int rem = idx & 32767;
    int b   = rem >> 9;
    int d   = rem & 511;
    int cap = captions[b * T_ + t];
    g_emb[idx] = embedding[(size_t)cap * D_ + d];
}

// ---------------- ctx0 = mean over L ---------------------------------------
__global__ void k_ctx0(const float* __restrict__ enc) {
    int idx = blockIdx.x * 256 + threadIdx.x;      // 0 .. B*F-1
    int b = idx >> 9, f = idx & 511;
    const float* p = enc + ((size_t)b * L_) * F_ + f;
    float s = 0.f;
    for (int l = 0; l < L_; ++l) s += p[(size_t)l * F_];
    g_ctx[idx] = s * (1.0f / (float)L_);
}

// ---------------- enc_proj GEMM: [12544,512] x [512,512]^T + be ------------
// C[m][n] = sum_k A[m][k] * W[n][k] + bias[n]
__global__ __launch_bounds__(256) void k_encproj(const float* __restrict__ A,
                                                 const float* __restrict__ W,
                                                 const float* __restrict__ bias) {
    __shared__ float As[16][128];
    __shared__ float Ws[16][64];
    int m0 = blockIdx.x * 128, n0 = blockIdx.y * 64;
    int tid = threadIdx.x, tx = tid & 15, ty = tid >> 4;
    float acc[8][4];
#pragma unroll
    for (int i = 0; i < 8; i++)
#pragma unroll
        for (int j = 0; j < 4; j++) acc[i][j] = 0.f;

    for (int k0 = 0; k0 < 512; k0 += 16) {
        {   // A tile 128x16
            int m = tid >> 1, kk = (tid & 1) * 8;
            const float* s = A + (size_t)(m0 + m) * 512 + k0 + kk;
            float4 v0 = *(const float4*)s;
            float4 v1 = *(const float4*)(s + 4);
            As[kk+0][m]=v0.x; As[kk+1][m]=v0.y; As[kk+2][m]=v0.z; As[kk+3][m]=v0.w;
            As[kk+4][m]=v1.x; As[kk+5][m]=v1.y; As[kk+6][m]=v1.z; As[kk+7][m]=v1.w;
        }
        {   // W tile 64x16
            int n = tid >> 2, kk = (tid & 3) * 4;
            float4 v = *(const float4*)(W + (size_t)(n0 + n) * 512 + k0 + kk);
            Ws[kk+0][n]=v.x; Ws[kk+1][n]=v.y; Ws[kk+2][n]=v.z; Ws[kk+3][n]=v.w;
        }
        __syncthreads();
#pragma unroll
        for (int k = 0; k < 16; ++k) {
            float a[8], bb[4];
            *(float4*)(a)     = *(const float4*)&As[k][ty*8];
            *(float4*)(a + 4) = *(const float4*)&As[k][ty*8 + 4];
            *(float4*)(bb)    = *(const float4*)&Ws[k][tx*4];
#pragma unroll
            for (int i = 0; i < 8; i++)
#pragma unroll
                for (int j = 0; j < 4; j++) acc[i][j] += a[i] * bb[j];
        }
        __syncthreads();
    }
    float4 bs = *(const float4*)(bias + n0 + tx * 4);
#pragma unroll
    for (int i = 0; i < 8; i++) {
        int m = m0 + ty * 8 + i;
        float4 r;
        r.x = acc[i][0] + bs.x; r.y = acc[i][1] + bs.y;
        r.z = acc[i][2] + bs.z; r.w = acc[i][3] + bs.w;
        *(float4*)&g_encproj[(size_t)m * 512 + n0 + tx * 4] = r;
    }
}

// ---------------- dec = h @ Wd^T + bd  (tiled, Wd read once) ---------------
__global__ __launch_bounds__(256) void k_dec(const float* __restrict__ Wd,
                                             const float* __restrict__ bd) {
    __shared__ float hs[64][65];
    __shared__ float ws[8][64];
    int n0 = blockIdx.x * 8;                   // 64 blocks x 8 columns
    int tid = threadIdx.x;
    int bq = tid & 63, jj = tid >> 6;          // jj in 0..3
    float acc0 = 0.f, acc1 = 0.f;
    for (int kb = 0; kb < 512; kb += 64) {
#pragma unroll
        for (int it = 0; it < 4; ++it) {       // h tile 64x64
            int r = (tid >> 4) + it * 16;
            int kk = (tid & 15) * 4;
            float4 v = *(const float4*)(g_h + (size_t)r * 512 + kb + kk);
            hs[r][kk+0]=v.x; hs[r][kk+1]=v.y; hs[r][kk+2]=v.z; hs[r][kk+3]=v.w;
        }
        if (tid < 128) {                       // Wd slice 8x64
            int n = tid >> 4, kk = (tid & 15) * 4;
            float4 v = *(const float4*)(Wd + (size_t)(n0 + n) * 512 + kb + kk);
            ws[n][kk+0]=v.x; ws[n][kk+1]=v.y; ws[n][kk+2]=v.z; ws[n][kk+3]=v.w;
        }
        __syncthreads();
#pragma unroll
        for (int k = 0; k < 64; ++k) {
            float hv = hs[bq][k];
            acc0 += hv * ws[jj][k];
            acc1 += hv * ws[jj + 4][k];
        }
        __syncthreads();
    }
    g_dec[(size_t)bq * 512 + n0 + jj]     = acc0 + bd[n0 + jj];
    g_dec[(size_t)bq * 512 + n0 + jj + 4] = acc1 + bd[n0 + jj + 4];
}

// ---------------- attention: scores -> softmax -> ctx ----------------------
__global__ __launch_bounds__(256) void k_attn(const float* __restrict__ enc,
                                              const float* __restrict__ vw,
                                              const float* __restrict__ vb) {
    __shared__ float dec_s[512];
    __shared__ float vw_s[512];
    __shared__ float sc[200];
    __shared__ float sred[256];
    int b = blockIdx.x;
    int tid = threadIdx.x;
    for (int i = tid; i < 512; i += 256) {
        dec_s[i] = g_dec[(size_t)b * 512 + i];
        vw_s[i]  = vw[i];
    }
    __syncthreads();
    int wid = tid >> 5, lane = tid & 31;
    float v_b = vb[0];
    for (int l = wid; l < L_; l += 8) {
        const float* ep = g_encproj + ((size_t)(b * L_ + l)) * 512;
        float s = 0.f;
        for (int hh = lane; hh < 512; hh += 32)
            s += tanhf(ep[hh] + dec_s[hh]) * vw_s[hh];
#pragma unroll
        for (int off = 16; off; off >>= 1) s += __shfl_xor_sync(0xffffffffu, s, off);
        if (lane == 0) sc[l] = s + v_b;
    }
    __syncthreads();
    // softmax over 196
    float mv = (tid < L_) ? sc[tid] : -1e30f;
    sred[tid] = mv; __syncthreads();
    for (int s = 128; s; s >>= 1) { if (tid < s) sred[tid] = fmaxf(sred[tid], sred[tid + s]); __syncthreads(); }
    float mx = sred[0]; __syncthreads();
    float ev = (tid < L_) ? expf(sc[tid] - mx) : 0.f;
    sred[tid] = ev; __syncthreads();
    for (int s = 128; s; s >>= 1) { if (tid < s) sred[tid] += sred[tid + s]; __syncthreads(); }
    float inv = 1.0f / sred[0]; __syncthreads();
    if (tid < L_) sc[tid] = ev * inv;
    __syncthreads();
    // ctx[b][f] = sum_l attn[l]*enc[b][l][f]
    for (int f = tid; f < F_; f += 256) {
        const float* eb = enc + ((size_t)b * L_) * F_ + f;
        float a = 0.f;
        for (int l = 0; l < L_; ++l) a += sc[l] * eb[(size_t)l * F_];
        g_ctx[(size_t)b * F_ + f] = a;
    }
}

// ---------------- LSTM gates GEMM (K-split partials) -----------------------
// C[gate][b] += sum_k Wrow[gate][k] * x[b][k]   over this split's K range
__global__ __launch_bounds__(256) void k_lstm_gemm(const float* __restrict__ W_ih,
                                                   const float* __restrict__ W_hh,
                                                   int t) {
    __shared__ float As[16][128];   // weight rows
    __shared__ float Bs[16][64];    // x columns (batch)
    int m0 = blockIdx.x * 128;      // gate rows
    int sp = blockIdx.y;            // K split
    int tid = threadIdx.x, tx = tid & 15, ty = tid >> 4;
    float acc[8][4];
#pragma unroll
    for (int i = 0; i < 8; i++)
#pragma unroll
        for (int j = 0; j < 4; j++) acc[i][j] = 0.f;

    const float* embt = g_emb + (size_t)t * B_ * 512;
    int kbeg = sp * KLEN_;
    for (int kv = kbeg; kv < kbeg + KLEN_; kv += 16) {
        {   // weights tile 128x16 (region uniform within 16-chunk)
            int m = tid >> 1, kk = (tid & 1) * 8;
            const float* src = (kv < 1024)
                ? (W_ih + (size_t)(m0 + m) * 1024 + kv + kk)
                : (W_hh + (size_t)(m0 + m) * 512 + (kv - 1024) + kk);
            float4 v0 = *(const float4*)src;
            float4 v1 = *(const float4*)(src + 4);
            As[kk+0][m]=v0.x; As[kk+1][m]=v0.y; As[kk+2][m]=v0.z; As[kk+3][m]=v0.w;
            As[kk+4][m]=v1.x; As[kk+5][m]=v1.y; As[kk+6][m]=v1.z; As[kk+7][m]=v1.w;
        }
        {   // x tile 64x16
            int n = tid >> 2, kk = (tid & 3) * 4;
            const float* src = (kv < 512)  ? (embt  + (size_t)n * 512 + kv + kk)
                             : (kv < 1024) ? (g_ctx + (size_t)n * 512 + (kv - 512) + kk)
                                           : (g_h   + (size_t)n * 512 + (kv - 1024) + kk);
            float4 v = *(const float4*)src;
            Bs[kk+0][n]=v.x; Bs[kk+1][n]=v.y; Bs[kk+2][n]=v.z; Bs[kk+3][n]=v.w;
        }
        __syncthreads();
#pragma unroll
        for (int k = 0; k < 16; ++k) {
            float a[8], bb[4];
            *(float4*)(a)     = *(const float4*)&As[k][ty*8];
            *(float4*)(a + 4) = *(const float4*)&As[k][ty*8 + 4];
            *(float4*)(bb)    = *(const float4*)&Bs[k][tx*4];
#pragma unroll
            for (int i = 0; i < 8; i++)
#pragma unroll
                for (int j = 0; j < 4; j++) acc[i][j] += a[i] * bb[j];
        }
        __syncthreads();
    }
#pragma unroll
    for (int i = 0; i < 8; i++) {
        int gm = m0 + ty * 8 + i;
        float4 r; r.x = acc[i][0]; r.y = acc[i][1]; r.z = acc[i][2]; r.w = acc[i][3];
        *(float4*)&g_gpart[((size_t)sp * G4_ + gm) * 64 + tx * 4] = r;
    }
}

// ---------------- LSTM pointwise: gates -> (h,c), store Hall[t] ------------
__global__ void k_point(const float* __restrict__ b_ih,
                        const float* __restrict__ b_hh, int t) {
    int idx = blockIdx.x * 256 + threadIdx.x;   // 0 .. B*H-1
    int b = idx & 63, h = idx >> 6;
    float gi = b_ih[h]        + b_hh[h];
    float gf = b_ih[h + 512]  + b_hh[h + 512];
    float gg = b_ih[h + 1024] + b_hh[h + 1024];
    float go = b_ih[h + 1536] + b_hh[h + 1536];
#pragma unroll
    for (int s = 0; s < KS_; ++s) {
        const float* p = g_gpart + (size_t)s * G4_ * 64;
        gi += p[(size_t)(h)        * 64 + b];
        gf += p[(size_t)(h + 512)  * 64 + b];
        gg += p[(size_t)(h + 1024) * 64 + b];
        go += p[(size_t)(h + 1536) * 64 + b];
    }
    float c  = g_c[(size_t)b * 512 + h];
    float si = 1.f / (1.f + expf(-gi));
    float sf = 1.f / (1.f + expf(-gf));
    float so = 1.f / (1.f + expf(-go));
    float c2 = sf * c + si * tanhf(gg);
    float h2 = so * tanhf(c2);
    g_c[(size_t)b * 512 + h] = c2;
    g_h[(size_t)b * 512 + h] = h2;
    g_Hall[((size_t)t * 64 + b) * 512 + h] = h2;
}

// ---------------- fc: out[b,t,:] = Hall[t*B+b] @ Wf^T + bf ----------------
__global__ __launch_bounds__(256) void k_fc(const float* __restrict__ Wf,
                                            const float* __restrict__ bf,
                                            float* __restrict__ out) {
    __shared__ float As[16][128];
    __shared__ float Ws[16][64];
    int m0 = blockIdx.x * 128, n0 = blockIdx.y * 64;
    int tid = threadIdx.x, tx = tid & 15, ty = tid >> 4;
    float acc[8][4];
#pragma unroll
    for (int i = 0; i < 8; i++)
#pragma unroll
        for (int j = 0; j < 4; j++) acc[i][j] = 0.f;

    for (int k0 = 0; k0 < 512; k0 += 16) {
        {   // Hall tile 128x16
            int m = tid >> 1, kk = (tid & 1) * 8;
            const float* s = g_Hall + (size_t)(m0 + m) * 512 + k0 + kk;
            float4 v0 = *(const float4*)s;
            float4 v1 = *(const float4*)(s + 4);
            As[kk+0][m]=v0.x; As[kk+1][m]=v0.y; As[kk+2][m]=v0.z; As[kk+3][m]=v0.w;
            As[kk+4][m]=v1.x; As[kk+5][m]=v1.y; As[kk+6][m]=v1.z; As[kk+7][m]=v1.w;
        }
        {   // Wf tile 64x16
            int n = tid >> 2, kk = (tid & 3) * 4;
            float4 v = *(const float4*)(Wf + (size_t)(n0 + n) * 512 + k0 + kk);
            Ws[kk+0][n]=v.x; Ws[kk+1][n]=v.y; Ws[kk+2][n]=v.z; Ws[kk+3][n]=v.w;
        }
        __syncthreads();
#pragma unroll
        for (int k = 0; k < 16; ++k) {
            float a[8], bb[4];
            *(float4*)(a)     = *(const float4*)&As[k][ty*8];
            *(float4*)(a + 4) = *(const float4*)&As[k][ty*8 + 4];
            *(float4*)(bb)    = *(const float4*)&Ws[k][tx*4];
#pragma unroll
            for (int i = 0; i < 8; i++)
#pragma unroll
                for (int j = 0; j < 4; j++) acc[i][j] += a[i] * bb[j];
        }
        __syncthreads();
    }
    float4 bs = *(const float4*)(bf + n0 + tx * 4);
#pragma unroll
    for (int i = 0; i < 8; i++) {
        int m = m0 + ty * 8 + i;
        int tcap = m >> 6, b = m & 63;
        float4 r;
        r.x = acc[i][0] + bs.x; r.y = acc[i][1] + bs.y;
        r.z = acc[i][2] + bs.z; r.w = acc[i][3] + bs.w;
        *(float4*)&out[((size_t)b * T_ + tcap) * V_ + n0 + tx * 4] = r;
    }
}

// ---------------- launch ----------------------------------------------------
extern "C" void kernel_launch(void* const* d_in, const int* in_sizes, int n_in,
                              void* d_out, int out_size) {
    const float* enc  = (const float*)d_in[0];
    const int*   caps = (const int*)  d_in[1];
    const float* emb  = (const float*)d_in[2];
    const float* We   = (const float*)d_in[3];
    const float* be   = (const float*)d_in[4];
    const float* Wd   = (const float*)d_in[5];
    const float* bd   = (const float*)d_in[6];
    const float* vw   = (const float*)d_in[7];
    const float* vb   = (const float*)d_in[8];
    const float* W_ih = (const float*)d_in[9];
    const float* W_hh = (const float*)d_in[10];
    const float* b_ih = (const float*)d_in[11];
    const float* b_hh = (const float*)d_in[12];
    const float* Wf   = (const float*)d_in[13];
    const float* bf   = (const float*)d_in[14];
    float* out = (float*)d_out;

    k_init<<<(T_ * B_ * D_) / 256, 256>>>(caps, emb);
    k_ctx0<<<(B_ * F_) / 256, 256>>>(enc);
    k_encproj<<<dim3(M_ENC / 128, H_ / 64), 256>>>(enc, We, be);

    for (int t = 0; t < T_; ++t) {
        if (t > 0) {
            k_dec<<<64, 256>>>(Wd, bd);
            k_attn<<<64, 256>>>(enc, vw, vb);
        }
        k_lstm_gemm<<<dim3(G4_ / 128, KS_), 256>>>(W_ih, W_hh, t);
        k_point<<<(B_ * H_) / 256, 256>>>(b_ih, b_hh, t);
    }

    k_fc<<<dim3(M_FC / 128, V_ / 64), 256>>>(Wf, bf, out);
}

// round 3
// speedup vs baseline: 1.4750x; 1.4750x over previous
#include <cuda_runtime.h>
#include <cuda_bf16.h>
#include <math.h>
#include <stdint.h>

// Problem constants
#define B_  64
#define L_  196
#define F_  512
#define T_  32
#define H_  512
#define D_  512
#define V_  32000
#define G4_ 2048               // 4*H
#define M_ENC (B_*L_)          // 12544
#define M_FC  (T_*B_)          // 2048
#define KS_ 8                  // K-splits for LSTM gates GEMM
#define KC_ 1536               // D+F+H

// ====================== warp-mma helpers (sm_80 baseline ISA) ==============
__device__ __forceinline__ uint32_t smem_to_u32(const void* p) {
    uint32_t a;
    asm("{ .reg .u64 t; cvta.to.shared.u64 t, %1; cvt.u32.u64 %0, t; }" : "=r"(a) : "l"(p));
    return a;
}

#define LDMX4(r0,r1,r2,r3,addr) \
    asm volatile("ldmatrix.sync.aligned.m8n8.x4.shared.b16 {%0,%1,%2,%3}, [%4];" \
        : "=r"(r0),"=r"(r1),"=r"(r2),"=r"(r3) : "r"(addr))

__device__ __forceinline__ void mma_bf16(float* c, const uint32_t* a, const uint32_t* b) {
    asm volatile(
        "mma.sync.aligned.m16n8k16.row.col.f32.bf16.bf16.f32 "
        "{%0,%1,%2,%3}, {%4,%5,%6,%7}, {%8,%9}, {%0,%1,%2,%3};"
        : "+f"(c[0]), "+f"(c[1]), "+f"(c[2]), "+f"(c[3])
        : "r"(a[0]), "r"(a[1]), "r"(a[2]), "r"(a[3]), "r"(b[0]), "r"(b[1]));
}

// ---------------- scratch (static device globals; no allocations) ----------
__device__ float g_encproj[M_ENC * H_];      // [B*L, H]
__device__ float g_emb[T_ * B_ * D_];        // [t, b, d]
__device__ float g_ctx[B_ * F_];             // current context
__device__ float g_h[B_ * H_];
__device__ float g_c[B_ * H_];
__device__ float g_dec[B_ * H_];
__device__ float g_Hall[T_ * B_ * H_];       // [(t*B+b), h]
__device__ float g_gpart[(size_t)KS_ * G4_ * B_]; // [s, gate, b]
// bf16 split operands
__device__ __nv_bfloat16 g_enc_hi[M_ENC * F_];
__device__ __nv_bfloat16 g_enc_lo[M_ENC * F_];
__device__ __nv_bfloat16 g_We_hi[H_ * F_];
__device__ __nv_bfloat16 g_We_lo[H_ * F_];
__device__ __nv_bfloat16 g_Wf_hi[(size_t)V_ * H_];
__device__ __nv_bfloat16 g_Wf_lo[(size_t)V_ * H_];
__device__ __nv_bfloat16 g_Hall_hi[M_FC * H_];
__device__ __nv_bfloat16 g_Hall_lo[M_FC * H_];
__device__ __nv_bfloat16 g_Wc_hi[(size_t)G4_ * KC_];  // [gate][k] cat(W_ih, W_hh)
__device__ __nv_bfloat16 g_Wc_lo[(size_t)G4_ * KC_];
__device__ __nv_bfloat16 g_xh[B_ * KC_];     // per-step x = [emb|ctx|h]
__device__ __nv_bfloat16 g_xl[B_ * KC_];

// ---------------- split fp32 -> bf16 hi/lo ---------------------------------
__global__ void k_split(const float* __restrict__ src,
                        __nv_bfloat16* __restrict__ hi,
                        __nv_bfloat16* __restrict__ lo) {
    size_t idx = (size_t)blockIdx.x * 256 + threadIdx.x;   // exact grid
    float x = src[idx];
    __nv_bfloat16 h = __float2bfloat16(x);
    hi[idx] = h;
    lo[idx] = __float2bfloat16(x - __bfloat162float(h));
}

// concat(W_ih, W_hh) -> bf16 hi/lo [2048][1536]
__global__ void k_wprep(const float* __restrict__ W_ih,
                        const float* __restrict__ W_hh) {
    size_t idx = (size_t)blockIdx.x * 256 + threadIdx.x;   // G4_*KC_ exact
    int m = (int)(idx / KC_), k = (int)(idx % KC_);
    float w = (k < 1024) ? W_ih[(size_t)m * 1024 + k]
                         : W_hh[(size_t)m * 512 + (k - 1024)];
    __nv_bfloat16 h = __float2bfloat16(w);
    g_Wc_hi[idx] = h;
    g_Wc_lo[idx] = __float2bfloat16(w - __bfloat162float(h));
}

// per-step x = [emb_t | ctx | h] -> bf16 hi/lo [64][1536]
__global__ void k_xprep(int t) {
    int idx = blockIdx.x * 256 + threadIdx.x;    // B_*KC_ = 98304 exact
    int b = idx / KC_, k = idx % KC_;
    float x = (k < 512)  ? g_emb[(size_t)t * B_ * 512 + (size_t)b * 512 + k]
            : (k < 1024) ? g_ctx[(size_t)b * 512 + (k - 512)]
                         : g_h[(size_t)b * 512 + (k - 1024)];
    __nv_bfloat16 h = __float2bfloat16(x);
    g_xh[idx] = h;
    g_xl[idx] = __float2bfloat16(x - __bfloat162float(h));
}

// ---------------- big GEMM (tile 128x128) via mma.sync bf16 3-pass ---------
// out[row(m), n0+n] = sum_k A[m,k]*B[n,k] + bias[n]
__global__ __launch_bounds__(256) void k_mma128(
    const __nv_bfloat16* __restrict__ Ahi, const __nv_bfloat16* __restrict__ Alo,
    const __nv_bfloat16* __restrict__ Bhi, const __nv_bfloat16* __restrict__ Blo,
    const float* __restrict__ bias, float* __restrict__ out,
    int K, int ldc, int fc_remap)
{
    __shared__ __nv_bfloat16 As[2][128 * 40];
    __shared__ __nv_bfloat16 Bs[2][128 * 40];
    int tid = threadIdx.x, wid = tid >> 5, lane = tid & 31;
    int m0 = blockIdx.x * 128, n0 = blockIdx.y * 128;
    int warp_m = wid & 1, warp_n = wid >> 1;   // 2 x 4 warp grid, warp tile 64x32

    float acc[4][4][4];
#pragma unroll
    for (int i = 0; i < 4; i++)
#pragma unroll
        for (int j = 0; j < 4; j++)
#pragma unroll
            for (int r = 0; r < 4; r++) acc[i][j][r] = 0.f;

    int sub = lane >> 3, ri = lane & 7;
    uint32_t aoff = (uint32_t)((((sub & 1) * 8 + ri) * 40 + (sub >> 1) * 8) * 2);
    uint32_t boff = (uint32_t)((((sub >> 1) * 8 + ri) * 40 + (sub & 1) * 8) * 2);
    uint32_t aAh = smem_to_u32(&As[0][0]) + (uint32_t)(warp_m * 64 * 40 * 2) + aoff;
    uint32_t aAl = smem_to_u32(&As[1][0]) + (uint32_t)(warp_m * 64 * 40 * 2) + aoff;
    uint32_t aBh = smem_to_u32(&Bs[0][0]) + (uint32_t)(warp_n * 32 * 40 * 2) + boff;
    uint32_t aBl = smem_to_u32(&Bs[1][0]) + (uint32_t)(warp_n * 32 * 40 * 2) + boff;

    for (int k0 = 0; k0 < K; k0 += 32) {
#pragma unroll
        for (int i = 0; i < 2; ++i) {
            int idx = tid + i * 256;           // 0..511
            int row = idx >> 2, q = idx & 3;
            int s = row * 40 + q * 8;
            size_t ga = (size_t)(m0 + row) * K + k0 + q * 8;
            size_t gb = (size_t)(n0 + row) * K + k0 + q * 8;
            *(uint4*)&As[0][s] = *(const uint4*)(Ahi + ga);
            *(uint4*)&As[1][s] = *(const uint4*)(Alo + ga);
            *(uint4*)&Bs[0][s] = *(const uint4*)(Bhi + gb);
            *(uint4*)&Bs[1][s] = *(const uint4*)(Blo + gb);
        }
        __syncthreads();
#pragma unroll
        for (int ks = 0; ks < 32; ks += 16) {
            uint32_t ah[4][4], al[4][4], bh[4][2], bl[4][2];
#pragma unroll
            for (int mi = 0; mi < 4; ++mi) {
                LDMX4(ah[mi][0], ah[mi][1], ah[mi][2], ah[mi][3],
                      aAh + (uint32_t)((mi * 16 * 40 + ks) * 2));
                LDMX4(al[mi][0], al[mi][1], al[mi][2], al[mi][3],
                      aAl + (uint32_t)((mi * 16 * 40 + ks) * 2));
            }
            LDMX4(bh[0][0], bh[0][1], bh[1][0], bh[1][1], aBh + (uint32_t)(ks * 2));
            LDMX4(bh[2][0], bh[2][1], bh[3][0], bh[3][1], aBh + (uint32_t)((16 * 40 + ks) * 2));
            LDMX4(bl[0][0], bl[0][1], bl[1][0], bl[1][1], aBl + (uint32_t)(ks * 2));
            LDMX4(bl[2][0], bl[2][1], bl[3][0], bl[3][1], aBl + (uint32_t)((16 * 40 + ks) * 2));
#pragma unroll
            for (int mi = 0; mi < 4; ++mi)
#pragma unroll
                for (int ni = 0; ni < 4; ++ni) {
                    mma_bf16(acc[mi][ni], ah[mi], bh[ni]);
                    mma_bf16(acc[mi][ni], ah[mi], bl[ni]);
                    mma_bf16(acc[mi][ni], al[mi], bh[ni]);
                }
        }
        __syncthreads();
    }

    int g = lane >> 2, t4 = lane & 3;
    float2 bv[4];
#pragma unroll
    for (int ni = 0; ni < 4; ++ni)
        bv[ni] = *(const float2*)(bias + n0 + warp_n * 32 + ni * 8 + 2 * t4);
#pragma unroll
    for (int mi = 0; mi < 4; ++mi)
#pragma unroll
        for (int rr = 0; rr < 2; ++rr) {
            int m = m0 + warp_m * 64 + mi * 16 + rr * 8 + g;
            int row = fc_remap ? ((m & 63) * T_ + (m >> 6)) : m;
            float* po = out + (size_t)row * ldc + n0 + warp_n * 32 + 2 * t4;
#pragma unroll
            for (int ni = 0; ni < 4; ++ni) {
                float2 v;
                v.x = acc[mi][ni][rr * 2 + 0] + bv[ni].x;
                v.y = acc[mi][ni][rr * 2 + 1] + bv[ni].y;
                *(float2*)(po + ni * 8) = v;
            }
        }
}

// ---------------- LSTM gates GEMM via mma (M=2048,N=64,K=1536 split x8) ----
__global__ __launch_bounds__(256) void k_lstm_mma() {
    __shared__ __nv_bfloat16 As[2][128 * 40];
    __shared__ __nv_bfloat16 Bs[2][64 * 40];
    int tid = threadIdx.x, wid = tid >> 5, lane = tid & 31;
    int m0 = blockIdx.x * 128;                 // 16 m-tiles
    int sp = blockIdx.y;                       // 8 K-splits
    int warp_m = wid >> 1, warp_n = wid & 1;   // 4 x 2 warp grid, warp tile 32x32

    float acc[2][4][4];
#pragma unroll
    for (int i = 0; i < 2; i++)
#pragma unroll
        for (int j = 0; j < 4; j++)
#pragma unroll
            for (int r = 0; r < 4; r++) acc[i][j][r] = 0.f;

    int sub = lane >> 3, ri = lane & 7;
    uint32_t aoff = (uint32_t)((((sub & 1) * 8 + ri) * 40 + (sub >> 1) * 8) * 2);
    uint32_t boff = (uint32_t)((((sub >> 1) * 8 + ri) * 40 + (sub & 1) * 8) * 2);
    uint32_t aAh = smem_to_u32(&As[0][0]) + (uint32_t)(warp_m * 32 * 40 * 2) + aoff;
    uint32_t aAl = smem_to_u32(&As[1][0]) + (uint32_t)(warp_m * 32 * 40 * 2) + aoff;
    uint32_t aBh = smem_to_u32(&Bs[0][0]) + (uint32_t)(warp_n * 32 * 40 * 2) + boff;
    uint32_t aBl = smem_to_u32(&Bs[1][0]) + (uint32_t)(warp_n * 32 * 40 * 2) + boff;

    int kbeg = sp * (KC_ / KS_);               // 192 per split
    for (int k0 = kbeg; k0 < kbeg + KC_ / KS_; k0 += 32) {
#pragma unroll
        for (int i = 0; i < 2; ++i) {
            int idx = tid + i * 256;
            int row = idx >> 2, q = idx & 3;
            int s = row * 40 + q * 8;
            size_t ga = (size_t)(m0 + row) * KC_ + k0 + q * 8;
            *(uint4*)&As[0][s] = *(const uint4*)(g_Wc_hi + ga);
            *(uint4*)&As[1][s] = *(const uint4*)(g_Wc_lo + ga);
        }
        {
            int row = tid >> 2, q = tid & 3;
            int s = row * 40 + q * 8;
            size_t gb = (size_t)row * KC_ + k0 + q * 8;
            *(uint4*)&Bs[0][s] = *(const uint4*)(g_xh + gb);
            *(uint4*)&Bs[1][s] = *(const uint4*)(g_xl + gb);
        }
        __syncthreads();
#pragma unroll
        for (int ks = 0; ks < 32; ks += 16) {
            uint32_t ah[2][4], al[2][4], bh[4][2], bl[4][2];
#pragma unroll
            for (int mi = 0; mi < 2; ++mi) {
                LDMX4(ah[mi][0], ah[mi][1], ah[mi][2], ah[mi][3],
                      aAh + (uint32_t)((mi * 16 * 40 + ks) * 2));
                LDMX4(al[mi][0], al[mi][1], al[mi][2], al[mi][3],
                      aAl + (uint32_t)((mi * 16 * 40 + ks) * 2));
            }
            LDMX4(bh[0][0], bh[0][1], bh[1][0], bh[1][1], aBh + (uint32_t)(ks * 2));
            LDMX4(bh[2][0], bh[2][1], bh[3][0], bh[3][1], aBh + (uint32_t)((16 * 40 + ks) * 2));
            LDMX4(bl[0][0], bl[0][1], bl[1][0], bl[1][1], aBl + (uint32_t)(ks * 2));
            LDMX4(bl[2][0], bl[2][1], bl[3][0], bl[3][1], aBl + (uint32_t)((16 * 40 + ks) * 2));
#pragma unroll
            for (int mi = 0; mi < 2; ++mi)
#pragma unroll
                for (int ni = 0; ni < 4; ++ni) {
                    mma_bf16(acc[mi][ni], ah[mi], bh[ni]);
                    mma_bf16(acc[mi][ni], ah[mi], bl[ni]);
                    mma_bf16(acc[mi][ni], al[mi], bh[ni]);
                }
        }
        __syncthreads();
    }

    float* base = g_gpart + (size_t)sp * G4_ * 64;
    int g = lane >> 2, t4 = lane & 3;
#pragma unroll
    for (int mi = 0; mi < 2; ++mi)
#pragma unroll
        for (int rr = 0; rr < 2; ++rr) {
            int m = m0 + warp_m * 32 + mi * 16 + rr * 8 + g;
            float* po = base + (size_t)m * 64 + warp_n * 32 + 2 * t4;
#pragma unroll
            for (int ni = 0; ni < 4; ++ni) {
                float2 v;
                v.x = acc[mi][ni][rr * 2 + 0];
                v.y = acc[mi][ni][rr * 2 + 1];
                *(float2*)(po + ni * 8) = v;
            }
        }
}

// ---------------- init: zero h/c, gather embeddings ------------------------
__global__ void k_init(const int* __restrict__ captions,
                       const float* __restrict__ embedding) {
    int idx = blockIdx.x * 256 + threadIdx.x;      // T*B*D exact
    if (idx < B_ * H_) { g_h[idx] = 0.f; g_c[idx] = 0.f; }
    int t   = idx >> 15;
    int rem = idx & 32767;
    int b   = rem >> 9;
    int d   = rem & 511;
    int cap = captions[b * T_ + t];
    g_emb[idx] = embedding[(size_t)cap * D_ + d];
}

// ---------------- ctx0 = mean over L ---------------------------------------
__global__ void k_ctx0(const float* __restrict__ enc) {
    int idx = blockIdx.x * 256 + threadIdx.x;      // B*F exact
    int b = idx >> 9, f = idx & 511;
    const float* p = enc + ((size_t)b * L_) * F_ + f;
    float s = 0.f;
    for (int l = 0; l < L_; ++l) s += p[(size_t)l * F_];
    g_ctx[idx] = s * (1.0f / (float)L_);
}

// ---------------- dec = h @ Wd^T + bd --------------------------------------
__global__ __launch_bounds__(256) void k_dec(const float* __restrict__ Wd,
                                             const float* __restrict__ bd) {
    __shared__ float hs[64][65];
    __shared__ float ws[8][64];
    int n0 = blockIdx.x * 8;
    int tid = threadIdx.x;
    int bq = tid & 63, jj = tid >> 6;
    float acc0 = 0.f, acc1 = 0.f;
    for (int kb = 0; kb < 512; kb += 64) {
#pragma unroll
        for (int it = 0; it < 4; ++it) {
            int r = (tid >> 4) + it * 16;
            int kk = (tid & 15) * 4;
            float4 v = *(const float4*)(g_h + (size_t)r * 512 + kb + kk);
            hs[r][kk+0]=v.x; hs[r][kk+1]=v.y; hs[r][kk+2]=v.z; hs[r][kk+3]=v.w;
        }
        if (tid < 128) {
            int n = tid >> 4, kk = (tid & 15) * 4;
            float4 v = *(const float4*)(Wd + (size_t)(n0 + n) * 512 + kb + kk);
            ws[n][kk+0]=v.x; ws[n][kk+1]=v.y; ws[n][kk+2]=v.z; ws[n][kk+3]=v.w;
        }
        __syncthreads();
#pragma unroll
        for (int k = 0; k < 64; ++k) {
            float hv = hs[bq][k];
            acc0 += hv * ws[jj][k];
            acc1 += hv * ws[jj + 4][k];
        }
        __syncthreads();
    }
    g_dec[(size_t)bq * 512 + n0 + jj]     = acc0 + bd[n0 + jj];
    g_dec[(size_t)bq * 512 + n0 + jj + 4] = acc1 + bd[n0 + jj + 4];
}

// ---------------- attention: scores -> softmax -> ctx ----------------------
__global__ __launch_bounds__(256) void k_attn(const float* __restrict__ enc,
                                              const float* __restrict__ vw,
                                              const float* __restrict__ vb) {
    __shared__ float dec_s[512];
    __shared__ float vw_s[512];
    __shared__ float sc[200];
    __shared__ float sred[256];
    int b = blockIdx.x;
    int tid = threadIdx.x;
    for (int i = tid; i < 512; i += 256) {
        dec_s[i] = g_dec[(size_t)b * 512 + i];
        vw_s[i]  = vw[i];
    }
    __syncthreads();
    int wid = tid >> 5, lane = tid & 31;
    float v_b = vb[0];
    for (int l = wid; l < L_; l += 8) {
        const float* ep = g_encproj + ((size_t)(b * L_ + l)) * 512;
        float s = 0.f;
        for (int hh = lane; hh < 512; hh += 32)
            s += tanhf(ep[hh] + dec_s[hh]) * vw_s[hh];
#pragma unroll
        for (int off = 16; off; off >>= 1) s += __shfl_xor_sync(0xffffffffu, s, off);
        if (lane == 0) sc[l] = s + v_b;
    }
    __syncthreads();
    float mv = (tid < L_) ? sc[tid] : -1e30f;
    sred[tid] = mv; __syncthreads();
    for (int s = 128; s; s >>= 1) { if (tid < s) sred[tid] = fmaxf(sred[tid], sred[tid + s]); __syncthreads(); }
    float mx = sred[0]; __syncthreads();
    float ev = (tid < L_) ? expf(sc[tid] - mx) : 0.f;
    sred[tid] = ev; __syncthreads();
    for (int s = 128; s; s >>= 1) { if (tid < s) sred[tid] += sred[tid + s]; __syncthreads(); }
    float inv = 1.0f / sred[0]; __syncthreads();
    if (tid < L_) sc[tid] = ev * inv;
    __syncthreads();
    for (int f = tid; f < F_; f += 256) {
        const float* eb = enc + ((size_t)b * L_) * F_ + f;
        float a = 0.f;
        for (int l = 0; l < L_; ++l) a += sc[l] * eb[(size_t)l * F_];
        g_ctx[(size_t)b * F_ + f] = a;
    }
}

// ---------------- LSTM pointwise: gates -> (h,c), store Hall[t] ------------
__global__ void k_point(const float* __restrict__ b_ih,
                        const float* __restrict__ b_hh, int t) {
    int idx = blockIdx.x * 256 + threadIdx.x;   // B*H exact
    int b = idx & 63, h = idx >> 6;
    float gi = b_ih[h]        + b_hh[h];
    float gf = b_ih[h + 512]  + b_hh[h + 512];
    float gg = b_ih[h + 1024] + b_hh[h + 1024];
    float go = b_ih[h + 1536] + b_hh[h + 1536];
#pragma unroll
    for (int s = 0; s < KS_; ++s) {
        const float* p = g_gpart + (size_t)s * G4_ * 64;
        gi += p[(size_t)(h)        * 64 + b];
        gf += p[(size_t)(h + 512)  * 64 + b];
        gg += p[(size_t)(h + 1024) * 64 + b];
        go += p[(size_t)(h + 1536) * 64 + b];
    }
    float c  = g_c[(size_t)b * 512 + h];
    float si = 1.f / (1.f + expf(-gi));
    float sf = 1.f / (1.f + expf(-gf));
    float so = 1.f / (1.f + expf(-go));
    float c2 = sf * c + si * tanhf(gg);
    float h2 = so * tanhf(c2);
    g_c[(size_t)b * 512 + h] = c2;
    g_h[(size_t)b * 512 + h] = h2;
    g_Hall[((size_t)t * 64 + b) * 512 + h] = h2;
}

// ---------------- launch ----------------------------------------------------
extern "C" void kernel_launch(void* const* d_in, const int* in_sizes, int n_in,
                              void* d_out, int out_size) {
    const float* enc  = (const float*)d_in[0];
    const int*   caps = (const int*)  d_in[1];
    const float* emb  = (const float*)d_in[2];
    const float* We   = (const float*)d_in[3];
    const float* be   = (const float*)d_in[4];
    const float* Wd   = (const float*)d_in[5];
    const float* bd   = (const float*)d_in[6];
    const float* vw   = (const float*)d_in[7];
    const float* vb   = (const float*)d_in[8];
    const float* W_ih = (const float*)d_in[9];
    const float* W_hh = (const float*)d_in[10];
    const float* b_ih = (const float*)d_in[11];
    const float* b_hh = (const float*)d_in[12];
    const float* Wf   = (const float*)d_in[13];
    const float* bf   = (const float*)d_in[14];
    float* out = (float*)d_out;

    void *p_enc_hi, *p_enc_lo, *p_We_hi, *p_We_lo, *p_Wf_hi, *p_Wf_lo,
         *p_Hall, *p_Hall_hi, *p_Hall_lo, *p_encproj;
    cudaGetSymbolAddress(&p_enc_hi, g_enc_hi);
    cudaGetSymbolAddress(&p_enc_lo, g_enc_lo);
    cudaGetSymbolAddress(&p_We_hi, g_We_hi);
    cudaGetSymbolAddress(&p_We_lo, g_We_lo);
    cudaGetSymbolAddress(&p_Wf_hi, g_Wf_hi);
    cudaGetSymbolAddress(&p_Wf_lo, g_Wf_lo);
    cudaGetSymbolAddress(&p_Hall, g_Hall);
    cudaGetSymbolAddress(&p_Hall_hi, g_Hall_hi);
    cudaGetSymbolAddress(&p_Hall_lo, g_Hall_lo);
    cudaGetSymbolAddress(&p_encproj, g_encproj);

    k_init<<<(T_ * B_ * D_) / 256, 256>>>(caps, emb);
    k_ctx0<<<(B_ * F_) / 256, 256>>>(enc);

    // split operands to bf16 hi/lo
    k_split<<<(M_ENC * F_) / 256, 256>>>(enc, (__nv_bfloat16*)p_enc_hi, (__nv_bfloat16*)p_enc_lo);
    k_split<<<(H_ * F_) / 256, 256>>>(We, (__nv_bfloat16*)p_We_hi, (__nv_bfloat16*)p_We_lo);
    k_split<<<((size_t)V_ * H_) / 256, 256>>>(Wf, (__nv_bfloat16*)p_Wf_hi, (__nv_bfloat16*)p_Wf_lo);
    k_wprep<<<((size_t)G4_ * KC_) / 256, 256>>>(W_ih, W_hh);

    // enc_proj = enc @ We^T + be
    k_mma128<<<dim3(M_ENC / 128, H_ / 128), 256>>>(
        (const __nv_bfloat16*)p_enc_hi, (const __nv_bfloat16*)p_enc_lo,
        (const __nv_bfloat16*)p_We_hi, (const __nv_bfloat16*)p_We_lo,
        be, (float*)p_encproj, F_, H_, 0);

    for (int t = 0; t < T_; ++t) {
        if (t > 0) {
            k_dec<<<64, 256>>>(Wd, bd);
            k_attn<<<64, 256>>>(enc, vw, vb);
        }
        k_xprep<<<(B_ * KC_) / 256, 256>>>(t);
        k_lstm_mma<<<dim3(G4_ / 128, KS_), 256>>>();
        k_point<<<(B_ * H_) / 256, 256>>>(b_ih, b_hh, t);
    }

    // fc logits: Hall @ Wf^T + bf
    k_split<<<(M_FC * H_) / 256, 256>>>((const float*)p_Hall,
                                        (__nv_bfloat16*)p_Hall_hi, (__nv_bfloat16*)p_Hall_lo);
    k_mma128<<<dim3(M_FC / 128, V_ / 128), 256>>>(
        (const __nv_bfloat16*)p_Hall_hi, (const __nv_bfloat16*)p_Hall_lo,
        (const __nv_bfloat16*)p_Wf_hi, (const __nv_bfloat16*)p_Wf_lo,
        bf, out, H_, V_, 1);
}

// round 4
// speedup vs baseline: 1.5679x; 1.0630x over previous
#include <cuda_runtime.h>
#include <cuda_bf16.h>
#include <math.h>
#include <stdint.h>

// Problem constants
#define B_  64
#define L_  196
#define F_  512
#define T_  32
#define H_  512
#define D_  512
#define V_  32000
#define G4_ 2048               // 4*H
#define M_ENC (B_*L_)          // 12544
#define M_FC  (T_*B_)          // 2048
#define KS_ 8                  // K-splits for LSTM gates GEMM
#define KC_ 1536               // D+F+H

// ====================== warp-mma helpers (sm_80 baseline ISA) ==============
__device__ __forceinline__ uint32_t smem_to_u32(const void* p) {
    uint32_t a;
    asm("{ .reg .u64 t; cvta.to.shared.u64 t, %1; cvt.u32.u64 %0, t; }" : "=r"(a) : "l"(p));
    return a;
}

#define LDMX4(r0,r1,r2,r3,addr) \
    asm volatile("ldmatrix.sync.aligned.m8n8.x4.shared.b16 {%0,%1,%2,%3}, [%4];" \
        : "=r"(r0),"=r"(r1),"=r"(r2),"=r"(r3) : "r"(addr))

#define CP16(dst, src) \
    asm volatile("cp.async.cg.shared.global [%0], [%1], 16;" :: "r"(dst), "l"(src))
#define CP_COMMIT() asm volatile("cp.async.commit_group;")
#define CP_WAIT(n)  asm volatile("cp.async.wait_group %0;" :: "n"(n))

__device__ __forceinline__ void mma_bf16(float* c, const uint32_t* a, const uint32_t* b) {
    asm volatile(
        "mma.sync.aligned.m16n8k16.row.col.f32.bf16.bf16.f32 "
        "{%0,%1,%2,%3}, {%4,%5,%6,%7}, {%8,%9}, {%0,%1,%2,%3};"
        : "+f"(c[0]), "+f"(c[1]), "+f"(c[2]), "+f"(c[3])
        : "r"(a[0]), "r"(a[1]), "r"(a[2]), "r"(a[3]), "r"(b[0]), "r"(b[1]));
}

__device__ __forceinline__ float ftanh(float x) {
    float e = __expf(2.0f * x);
    return 1.0f - __fdividef(2.0f, e + 1.0f);
}

// ---------------- scratch (static device globals; no allocations) ----------
__device__ float g_encproj[M_ENC * H_];      // [B*L, H]
__device__ float g_emb[T_ * B_ * D_];        // [t, b, d]
__device__ float g_ctx[B_ * F_];             // current context
__device__ float g_h[B_ * H_];
__device__ float g_c[B_ * H_];
__device__ float g_dec[B_ * H_];
__device__ float g_score[B_ * L_];
__device__ float g_Hall[T_ * B_ * H_];       // [(t*B+b), h]
__device__ float g_gpart[(size_t)KS_ * G4_ * B_]; // [s, gate, b]
// bf16 split operands
__device__ __nv_bfloat16 g_enc_hi[M_ENC * F_];
__device__ __nv_bfloat16 g_enc_lo[M_ENC * F_];
__device__ __nv_bfloat16 g_We_hi[H_ * F_];
__device__ __nv_bfloat16 g_We_lo[H_ * F_];
__device__ __nv_bfloat16 g_Wf_hi[(size_t)V_ * H_];
__device__ __nv_bfloat16 g_Wf_lo[(size_t)V_ * H_];
__device__ __nv_bfloat16 g_Hall_hi[M_FC * H_];
__device__ __nv_bfloat16 g_Hall_lo[M_FC * H_];
__device__ __nv_bfloat16 g_Wc_hi[(size_t)G4_ * KC_];  // [gate][k] cat(W_ih, W_hh)
__device__ __nv_bfloat16 g_Wc_lo[(size_t)G4_ * KC_];

// ---------------- split fp32 -> bf16 hi/lo ---------------------------------
__global__ void k_split(const float* __restrict__ src,
                        __nv_bfloat16* __restrict__ hi,
                        __nv_bfloat16* __restrict__ lo) {
    size_t idx = (size_t)blockIdx.x * 256 + threadIdx.x;   // exact grid
    float x = src[idx];
    __nv_bfloat16 h = __float2bfloat16(x);
    hi[idx] = h;
    lo[idx] = __float2bfloat16(x - __bfloat162float(h));
}

// concat(W_ih, W_hh) -> bf16 hi/lo [2048][1536]
__global__ void k_wprep(const float* __restrict__ W_ih,
                        const float* __restrict__ W_hh) {
    size_t idx = (size_t)blockIdx.x * 256 + threadIdx.x;   // G4_*KC_ exact
    int m = (int)(idx / KC_), k = (int)(idx % KC_);
    float w = (k < 1024) ? W_ih[(size_t)m * 1024 + k]
                         : W_hh[(size_t)m * 512 + (k - 1024)];
    __nv_bfloat16 h = __float2bfloat16(w);
    g_Wc_hi[idx] = h;
    g_Wc_lo[idx] = __float2bfloat16(w - __bfloat162float(h));
}

// ---------------- big GEMM (tile 128x128) cp.async pipelined 3-pass --------
// out[row(m), n0+n] = sum_k A[m,k]*B[n,k] + bias[n];  K multiple of 64
#define TILE_ELEM (128 * 72)            // one tile: 128 rows x 64 cols + 8 pad
#define TILE_B    (TILE_ELEM * 2)       // 18432 bytes
#define PIPE_SMEM (TILE_B * 8)          // 2 stages x 4 tiles = 147456 bytes

__global__ __launch_bounds__(256) void k_mma128(
    const __nv_bfloat16* __restrict__ Ahi, const __nv_bfloat16* __restrict__ Alo,
    const __nv_bfloat16* __restrict__ Bhi, const __nv_bfloat16* __restrict__ Blo,
    const float* __restrict__ bias, float* __restrict__ out,
    int K, int ldc, int fc_remap)
{
    extern __shared__ char smem[];
    uint32_t sb = smem_to_u32(smem);
    int tid = threadIdx.x, wid = tid >> 5, lane = tid & 31;
    int m0 = blockIdx.x * 128, n0 = blockIdx.y * 128;
    int warp_m = wid & 1, warp_n = wid >> 1;   // 2 x 4 warp grid, warp tile 64x32

    float acc[4][4][4];
#pragma unroll
    for (int i = 0; i < 4; i++)
#pragma unroll
        for (int j = 0; j < 4; j++)
#pragma unroll
            for (int r = 0; r < 4; r++) acc[i][j][r] = 0.f;

    int row_ld = tid >> 1, q_ld = tid & 1;     // loader: 4 consecutive 16B per (row,half)
    int sub = lane >> 3, ri = lane & 7;
    uint32_t aoff = (uint32_t)((((sub & 1) * 8 + ri) * 72 + (sub >> 1) * 8) * 2)
                  + (uint32_t)(warp_m * 64 * 144);
    uint32_t boff = (uint32_t)((((sub >> 1) * 8 + ri) * 72 + (sub & 1) * 8) * 2)
                  + (uint32_t)(warp_n * 32 * 144);

    int NC = K >> 6;

    // issue chunk c into stage s
#define ISSUE(c, s) do { \
        int k0 = (c) << 6; \
        uint32_t st = sb + (uint32_t)((s) * 4 * TILE_B); \
        size_t gA = (size_t)(m0 + row_ld) * K + k0 + q_ld * 32; \
        size_t gB = (size_t)(n0 + row_ld) * K + k0 + q_ld * 32; \
        uint32_t so = (uint32_t)((row_ld * 72 + q_ld * 32) * 2); \
        _Pragma("unroll") \
        for (int qq = 0; qq < 4; ++qq) { \
            CP16(st + 0 * TILE_B + so + qq * 16, Ahi + gA + qq * 8); \
            CP16(st + 1 * TILE_B + so + qq * 16, Alo + gA + qq * 8); \
            CP16(st + 2 * TILE_B + so + qq * 16, Bhi + gB + qq * 8); \
            CP16(st + 3 * TILE_B + so + qq * 16, Blo + gB + qq * 8); \
        } \
        CP_COMMIT(); \
    } while (0)

    ISSUE(0, 0);
    for (int c = 0; c < NC; ++c) {
        int s = c & 1;
        if (c + 1 < NC) { ISSUE(c + 1, (c + 1) & 1); CP_WAIT(1); }
        else           { CP_WAIT(0); }
        __syncthreads();
        uint32_t bAh = sb + (uint32_t)(s * 4 * TILE_B) + aoff;
        uint32_t bAl = bAh + TILE_B;
        uint32_t bBh = sb + (uint32_t)(s * 4 * TILE_B + 2 * TILE_B) + boff;
        uint32_t bBl = bBh + TILE_B;
#pragma unroll
        for (int ks = 0; ks < 64; ks += 16) {
            uint32_t ah[4][4], al[4][4], bh[4][2], bl[4][2];
#pragma unroll
            for (int mi = 0; mi < 4; ++mi) {
                LDMX4(ah[mi][0], ah[mi][1], ah[mi][2], ah[mi][3],
                      bAh + (uint32_t)(mi * 16 * 144 + ks * 2));
                LDMX4(al[mi][0], al[mi][1], al[mi][2], al[mi][3],
                      bAl + (uint32_t)(mi * 16 * 144 + ks * 2));
            }
            LDMX4(bh[0][0], bh[0][1], bh[1][0], bh[1][1], bBh + (uint32_t)(ks * 2));
            LDMX4(bh[2][0], bh[2][1], bh[3][0], bh[3][1], bBh + (uint32_t)(16 * 144 + ks * 2));
            LDMX4(bl[0][0], bl[0][1], bl[1][0], bl[1][1], bBl + (uint32_t)(ks * 2));
            LDMX4(bl[2][0], bl[2][1], bl[3][0], bl[3][1], bBl + (uint32_t)(16 * 144 + ks * 2));
#pragma unroll
            for (int mi = 0; mi < 4; ++mi)
#pragma unroll
                for (int ni = 0; ni < 4; ++ni) {
                    mma_bf16(acc[mi][ni], ah[mi], bh[ni]);
                    mma_bf16(acc[mi][ni], ah[mi], bl[ni]);
                    mma_bf16(acc[mi][ni], al[mi], bh[ni]);
                }
        }
        __syncthreads();
    }
#undef ISSUE

    int g = lane >> 2, t4 = lane & 3;
    float2 bv[4];
#pragma unroll
    for (int ni = 0; ni < 4; ++ni)
        bv[ni] = *(const float2*)(bias + n0 + warp_n * 32 + ni * 8 + 2 * t4);
#pragma unroll
    for (int mi = 0; mi < 4; ++mi)
#pragma unroll
        for (int rr = 0; rr < 2; ++rr) {
            int m = m0 + warp_m * 64 + mi * 16 + rr * 8 + g;
            int row = fc_remap ? ((m & 63) * T_ + (m >> 6)) : m;
            float* po = out + (size_t)row * ldc + n0 + warp_n * 32 + 2 * t4;
#pragma unroll
            for (int ni = 0; ni < 4; ++ni) {
                float2 v;
                v.x = acc[mi][ni][rr * 2 + 0] + bv[ni].x;
                v.y = acc[mi][ni][rr * 2 + 1] + bv[ni].y;
                *(float2*)(po + ni * 8) = v;
            }
        }
}

// ---------------- LSTM gates GEMM via mma (M=2048,N=64,K=1536 split x8) ----
// B operand (x = [emb_t | ctx | h]) converted fp32 -> bf16 hi/lo inline.
__global__ __launch_bounds__(256) void k_lstm_mma(int t) {
    __shared__ __nv_bfloat16 As[2][128 * 40];
    __shared__ __nv_bfloat16 Bs[2][64 * 40];
    int tid = threadIdx.x, wid = tid >> 5, lane = tid & 31;
    int m0 = blockIdx.x * 128;                 // 16 m-tiles
    int sp = blockIdx.y;                       // 8 K-splits
    int warp_m = wid >> 1, warp_n = wid & 1;   // 4 x 2 warp grid, warp tile 32x32

    float acc[2][4][4];
#pragma unroll
    for (int i = 0; i < 2; i++)
#pragma unroll
        for (int j = 0; j < 4; j++)
#pragma unroll
            for (int r = 0; r < 4; r++) acc[i][j][r] = 0.f;

    int sub = lane >> 3, ri = lane & 7;
    uint32_t aoff = (uint32_t)((((sub & 1) * 8 + ri) * 40 + (sub >> 1) * 8) * 2);
    uint32_t boff = (uint32_t)((((sub >> 1) * 8 + ri) * 40 + (sub & 1) * 8) * 2);
    uint32_t aAh = smem_to_u32(&As[0][0]) + (uint32_t)(warp_m * 32 * 40 * 2) + aoff;
    uint32_t aAl = smem_to_u32(&As[1][0]) + (uint32_t)(warp_m * 32 * 40 * 2) + aoff;
    uint32_t aBh = smem_to_u32(&Bs[0][0]) + (uint32_t)(warp_n * 32 * 40 * 2) + boff;
    uint32_t aBl = smem_to_u32(&Bs[1][0]) + (uint32_t)(warp_n * 32 * 40 * 2) + boff;

    const float* embt = g_emb + (size_t)t * B_ * 512;
    int kbeg = sp * (KC_ / KS_);               // 192 per split
    for (int k0 = kbeg; k0 < kbeg + KC_ / KS_; k0 += 32) {
#pragma unroll
        for (int i = 0; i < 2; ++i) {
            int idx = tid + i * 256;
            int row = idx >> 2, q = idx & 3;
            int s = row * 40 + q * 8;
            size_t ga = (size_t)(m0 + row) * KC_ + k0 + q * 8;
            *(uint4*)&As[0][s] = *(const uint4*)(g_Wc_hi + ga);
            *(uint4*)&As[1][s] = *(const uint4*)(g_Wc_lo + ga);
        }
        {   // B tile 64 rows x 32 cols, converted on the fly (2 float4 / thread)
#pragma unroll
            for (int i = 0; i < 2; ++i) {
                int idx = tid + i * 256;            // 0..511
                int row = idx >> 3, q = idx & 7;    // col = q*4
                int kk = k0 + q * 4;
                const float* src = (kk < 512)  ? (embt  + (size_t)row * 512 + kk)
                                 : (kk < 1024) ? (g_ctx + (size_t)row * 512 + kk - 512)
                                               : (g_h   + (size_t)row * 512 + kk - 1024);
                float4 v = *(const float4*)src;
                __nv_bfloat16 hx = __float2bfloat16(v.x), hy = __float2bfloat16(v.y);
                __nv_bfloat16 hz = __float2bfloat16(v.z), hw = __float2bfloat16(v.w);
                int s = row * 40 + q * 4;
                Bs[0][s+0]=hx; Bs[0][s+1]=hy; Bs[0][s+2]=hz; Bs[0][s+3]=hw;
                Bs[1][s+0]=__float2bfloat16(v.x - __bfloat162float(hx));
                Bs[1][s+1]=__float2bfloat16(v.y - __bfloat162float(hy));
                Bs[1][s+2]=__float2bfloat16(v.z - __bfloat162float(hz));
                Bs[1][s+3]=__float2bfloat16(v.w - __bfloat162float(hw));
            }
        }
        __syncthreads();
#pragma unroll
        for (int ks = 0; ks < 32; ks += 16) {
            uint32_t ah[2][4], al[2][4], bh[4][2], bl[4][2];
#pragma unroll
            for (int mi = 0; mi < 2; ++mi) {
                LDMX4(ah[mi][0], ah[mi][1], ah[mi][2], ah[mi][3],
                      aAh + (uint32_t)((mi * 16 * 40 + ks) * 2));
                LDMX4(al[mi][0], al[mi][1], al[mi][2], al[mi][3],
                      aAl + (uint32_t)((mi * 16 * 40 + ks) * 2));
            }
            LDMX4(bh[0][0], bh[0][1], bh[1][0], bh[1][1], aBh + (uint32_t)(ks * 2));
            LDMX4(bh[2][0], bh[2][1], bh[3][0], bh[3][1], aBh + (uint32_t)((16 * 40 + ks) * 2));
            LDMX4(bl[0][0], bl[0][1], bl[1][0], bl[1][1], aBl + (uint32_t)(ks * 2));
            LDMX4(bl[2][0], bl[2][1], bl[3][0], bl[3][1], aBl + (uint32_t)((16 * 40 + ks) * 2));
#pragma unroll
            for (int mi = 0; mi < 2; ++mi)
#pragma unroll
                for (int ni = 0; ni < 4; ++ni) {
                    mma_bf16(acc[mi][ni], ah[mi], bh[ni]);
                    mma_bf16(acc[mi][ni], ah[mi], bl[ni]);
                    mma_bf16(acc[mi][ni], al[mi], bh[ni]);
                }
        }
        __syncthreads();
    }

    float* base = g_gpart + (size_t)sp * G4_ * 64;
    int g = lane >> 2, t4 = lane & 3;
#pragma unroll
    for (int mi = 0; mi < 2; ++mi)
#pragma unroll
        for (int rr = 0; rr < 2; ++rr) {
            int m = m0 + warp_m * 32 + mi * 16 + rr * 8 + g;
            float* po = base + (size_t)m * 64 + warp_n * 32 + 2 * t4;
#pragma unroll
            for (int ni = 0; ni < 4; ++ni) {
                float2 v;
                v.x = acc[mi][ni][rr * 2 + 0];
                v.y = acc[mi][ni][rr * 2 + 1];
                *(float2*)(po + ni * 8) = v;
            }
        }
}

// ---------------- init: zero h/c, gather embeddings ------------------------
__global__ void k_init(const int* __restrict__ captions,
                       const float* __restrict__ embedding) {
    int idx = blockIdx.x * 256 + threadIdx.x;      // T*B*D exact
    if (idx < B_ * H_) { g_h[idx] = 0.f; g_c[idx] = 0.f; }
    int t   = idx >> 15;
    int rem = idx & 32767;
    int b   = rem >> 9;
    int d   = rem & 511;
    int cap = captions[b * T_ + t];
    g_emb[idx] = embedding[(size_t)cap * D_ + d];
}

// ---------------- ctx0 = mean over L ---------------------------------------
__global__ void k_ctx0(const float* __restrict__ enc) {
    int idx = blockIdx.x * 256 + threadIdx.x;      // B*F exact
    int b = idx >> 9, f = idx & 511;
    const float* p = enc + ((size_t)b * L_) * F_ + f;
    float s = 0.f;
    for (int l = 0; l < L_; ++l) s += p[(size_t)l * F_];
    g_ctx[idx] = s * (1.0f / (float)L_);
}

// ---------------- dec = h @ Wd^T + bd --------------------------------------
__global__ __launch_bounds__(256) void k_dec(const float* __restrict__ Wd,
                                             const float* __restrict__ bd) {
    __shared__ float hs[64][65];
    __shared__ float ws[8][64];
    int n0 = blockIdx.x * 8;
    int tid = threadIdx.x;
    int bq = tid & 63, jj = tid >> 6;
    float acc0 = 0.f, acc1 = 0.f;
    for (int kb = 0; kb < 512; kb += 64) {
#pragma unroll
        for (int it = 0; it < 4; ++it) {
            int r = (tid >> 4) + it * 16;
            int kk = (tid & 15) * 4;
            float4 v = *(const float4*)(g_h + (size_t)r * 512 + kb + kk);
            hs[r][kk+0]=v.x; hs[r][kk+1]=v.y; hs[r][kk+2]=v.z; hs[r][kk+3]=v.w;
        }
        if (tid < 128) {
            int n = tid >> 4, kk = (tid & 15) * 4;
            float4 v = *(const float4*)(Wd + (size_t)(n0 + n) * 512 + kb + kk);
            ws[n][kk+0]=v.x; ws[n][kk+1]=v.y; ws[n][kk+2]=v.z; ws[n][kk+3]=v.w;
        }
        __syncthreads();
#pragma unroll
        for (int k = 0; k < 64; ++k) {
            float hv = hs[bq][k];
            acc0 += hv * ws[jj][k];
            acc1 += hv * ws[jj + 4][k];
        }
        __syncthreads();
    }
    g_dec[(size_t)bq * 512 + n0 + jj]     = acc0 + bd[n0 + jj];
    g_dec[(size_t)bq * 512 + n0 + jj + 4] = acc1 + bd[n0 + jj + 4];
}

// ---------------- scores: tanh(enc_proj + dec) . v_w + v_b -----------------
__global__ __launch_bounds__(256) void k_scores(const float* __restrict__ vw,
                                                const float* __restrict__ vb) {
    __shared__ float dec_s[512];
    __shared__ float vw_s[512];
    int b = blockIdx.x, half = blockIdx.y;
    int tid = threadIdx.x;
    for (int i = tid; i < 512; i += 256) {
        dec_s[i] = g_dec[(size_t)b * 512 + i];
        vw_s[i]  = vw[i];
    }
    __syncthreads();
    int wid = tid >> 5, lane = tid & 31;
    float v_b = vb[0];
    int lend = (half == 0) ? 98 : L_;
    for (int l = half * 98 + wid; l < lend; l += 8) {
        const float* ep = g_encproj + ((size_t)(b * L_ + l)) * 512;
        float s = 0.f;
        for (int hh = lane; hh < 512; hh += 32)
            s += ftanh(ep[hh] + dec_s[hh]) * vw_s[hh];
#pragma unroll
        for (int off = 16; off; off >>= 1) s += __shfl_xor_sync(0xffffffffu, s, off);
        if (lane == 0) g_score[b * L_ + l] = s + v_b;
    }
}

// ---------------- softmax + ctx --------------------------------------------
__global__ __launch_bounds__(256) void k_softctx(const float* __restrict__ enc) {
    __shared__ float sc[200];
    __shared__ float sred[256];
    int b = blockIdx.x;
    int tid = threadIdx.x;
    float mv = (tid < L_) ? g_score[b * L_ + tid] : -1e30f;
    if (tid < L_) sc[tid] = mv;
    sred[tid] = mv; __syncthreads();
    for (int s = 128; s; s >>= 1) { if (tid < s) sred[tid] = fmaxf(sred[tid], sred[tid + s]); __syncthreads(); }
    float mx = sred[0]; __syncthreads();
    float ev = (tid < L_) ? __expf(sc[tid] - mx) : 0.f;
    sred[tid] = ev; __syncthreads();
    for (int s = 128; s; s >>= 1) { if (tid < s) sred[tid] += sred[tid + s]; __syncthreads(); }
    float inv = 1.0f / sred[0]; __syncthreads();
    if (tid < L_) sc[tid] = ev * inv;
    __syncthreads();
    for (int f = tid; f < F_; f += 256) {
        const float* eb = enc + ((size_t)b * L_) * F_ + f;
        float a = 0.f;
        for (int l = 0; l < L_; ++l) a += sc[l] * eb[(size_t)l * F_];
        g_ctx[(size_t)b * F_ + f] = a;
    }
}

// ---------------- LSTM pointwise: gates -> (h,c), store Hall[t] ------------
__global__ void k_point(const float* __restrict__ b_ih,
                        const float* __restrict__ b_hh, int t) {
    int idx = blockIdx.x * 256 + threadIdx.x;   // B*H exact
    int b = idx & 63, h = idx >> 6;
    float gi = b_ih[h]        + b_hh[h];
    float gf = b_ih[h + 512]  + b_hh[h + 512];
    float gg = b_ih[h + 1024] + b_hh[h + 1024];
    float go = b_ih[h + 1536] + b_hh[h + 1536];
#pragma unroll
    for (int s = 0; s < KS_; ++s) {
        const float* p = g_gpart + (size_t)s * G4_ * 64;
        gi += p[(size_t)(h)        * 64 + b];
        gf += p[(size_t)(h + 512)  * 64 + b];
        gg += p[(size_t)(h + 1024) * 64 + b];
        go += p[(size_t)(h + 1536) * 64 + b];
    }
    float c  = g_c[(size_t)b * 512 + h];
    float si = 1.f / (1.f + expf(-gi));
    float sf = 1.f / (1.f + expf(-gf));
    float so = 1.f / (1.f + expf(-go));
    float c2 = sf * c + si * tanhf(gg);
    float h2 = so * tanhf(c2);
    g_c[(size_t)b * 512 + h] = c2;
    g_h[(size_t)b * 512 + h] = h2;
    g_Hall[((size_t)t * 64 + b) * 512 + h] = h2;
}

// ---------------- launch ----------------------------------------------------
extern "C" void kernel_launch(void* const* d_in, const int* in_sizes, int n_in,
                              void* d_out, int out_size) {
    const float* enc  = (const float*)d_in[0];
    const int*   caps = (const int*)  d_in[1];
    const float* emb  = (const float*)d_in[2];
    const float* We   = (const float*)d_in[3];
    const float* be   = (const float*)d_in[4];
    const float* Wd   = (const float*)d_in[5];
    const float* bd   = (const float*)d_in[6];
    const float* vw   = (const float*)d_in[7];
    const float* vb   = (const float*)d_in[8];
    const float* W_ih = (const float*)d_in[9];
    const float* W_hh = (const float*)d_in[10];
    const float* b_ih = (const float*)d_in[11];
    const float* b_hh = (const float*)d_in[12];
    const float* Wf   = (const float*)d_in[13];
    const float* bf   = (const float*)d_in[14];
    float* out = (float*)d_out;

    cudaFuncSetAttribute(k_mma128, cudaFuncAttributeMaxDynamicSharedMemorySize, PIPE_SMEM);

    void *p_enc_hi, *p_enc_lo, *p_We_hi, *p_We_lo, *p_Wf_hi, *p_Wf_lo,
         *p_Hall, *p_Hall_hi, *p_Hall_lo, *p_encproj;
    cudaGetSymbolAddress(&p_enc_hi, g_enc_hi);
    cudaGetSymbolAddress(&p_enc_lo, g_enc_lo);
    cudaGetSymbolAddress(&p_We_hi, g_We_hi);
    cudaGetSymbolAddress(&p_We_lo, g_We_lo);
    cudaGetSymbolAddress(&p_Wf_hi, g_Wf_hi);
    cudaGetSymbolAddress(&p_Wf_lo, g_Wf_lo);
    cudaGetSymbolAddress(&p_Hall, g_Hall);
    cudaGetSymbolAddress(&p_Hall_hi, g_Hall_hi);
    cudaGetSymbolAddress(&p_Hall_lo, g_Hall_lo);
    cudaGetSymbolAddress(&p_encproj, g_encproj);

    k_init<<<(T_ * B_ * D_) / 256, 256>>>(caps, emb);
    k_ctx0<<<(B_ * F_) / 256, 256>>>(enc);

    // split operands to bf16 hi/lo
    k_split<<<(M_ENC * F_) / 256, 256>>>(enc, (__nv_bfloat16*)p_enc_hi, (__nv_bfloat16*)p_enc_lo);
    k_split<<<(H_ * F_) / 256, 256>>>(We, (__nv_bfloat16*)p_We_hi, (__nv_bfloat16*)p_We_lo);
    k_split<<<((size_t)V_ * H_) / 256, 256>>>(Wf, (__nv_bfloat16*)p_Wf_hi, (__nv_bfloat16*)p_Wf_lo);
    k_wprep<<<((size_t)G4_ * KC_) / 256, 256>>>(W_ih, W_hh);

    // enc_proj = enc @ We^T + be
    k_mma128<<<dim3(M_ENC / 128, H_ / 128), 256, PIPE_SMEM>>>(
        (const __nv_bfloat16*)p_enc_hi, (const __nv_bfloat16*)p_enc_lo,
        (const __nv_bfloat16*)p_We_hi, (const __nv_bfloat16*)p_We_lo,
        be, (float*)p_encproj, F_, H_, 0);

    for (int t = 0; t < T_; ++t) {
        if (t > 0) {
            k_dec<<<64, 256>>>(Wd, bd);
            k_scores<<<dim3(64, 2), 256>>>(vw, vb);
            k_softctx<<<64, 256>>>(enc);
        }
        k_lstm_mma<<<dim3(G4_ / 128, KS_), 256>>>(t);
        k_point<<<(B_ * H_) / 256, 256>>>(b_ih, b_hh, t);
    }

    // fc logits: Hall @ Wf^T + bf
    k_split<<<(M_FC * H_) / 256, 256>>>((const float*)p_Hall,
                                        (__nv_bfloat16*)p_Hall_hi, (__nv_bfloat16*)p_Hall_lo);
    k_mma128<<<dim3(M_FC / 128, V_ / 128), 256, PIPE_SMEM>>>(
        (const __nv_bfloat16*)p_Hall_hi, (const __nv_bfloat16*)p_Hall_lo,
        (const __nv_bfloat16*)p_Wf_hi, (const __nv_bfloat16*)p_Wf_lo,
        bf, out, H_, V_, 1);
}

// round 5
// speedup vs baseline: 1.6418x; 1.0472x over previous
#include <cuda_runtime.h>
#include <cuda_bf16.h>
#include <math.h>
#include <stdint.h>

// Problem constants
#define B_  64
#define L_  196
#define F_  512
#define T_  32
#define H_  512
#define D_  512
#define V_  32000
#define G4_ 2048               // 4*H
#define M_ENC (B_*L_)          // 12544
#define M_FC  (T_*B_)          // 2048
#define KS_ 8                  // K-splits for LSTM gates GEMM
#define KC_ 1536               // D+F+H
#define GRID_P 128             // persistent-loop grid (must be <= #SMs)

// ====================== warp-mma helpers (sm_80 baseline ISA) ==============
__device__ __forceinline__ uint32_t smem_to_u32(const void* p) {
    uint32_t a;
    asm("{ .reg .u64 t; cvta.to.shared.u64 t, %1; cvt.u32.u64 %0, t; }" : "=r"(a) : "l"(p));
    return a;
}

#define LDMX4(r0,r1,r2,r3,addr) \
    asm volatile("ldmatrix.sync.aligned.m8n8.x4.shared.b16 {%0,%1,%2,%3}, [%4];" \
        : "=r"(r0),"=r"(r1),"=r"(r2),"=r"(r3) : "r"(addr))

#define CP16(dst, src) \
    asm volatile("cp.async.cg.shared.global [%0], [%1], 16;" :: "r"(dst), "l"(src))
#define CP_COMMIT() asm volatile("cp.async.commit_group;")
#define CP_WAIT(n)  asm volatile("cp.async.wait_group %0;" :: "n"(n))

__device__ __forceinline__ void mma_bf16(float* c, const uint32_t* a, const uint32_t* b) {
    asm volatile(
        "mma.sync.aligned.m16n8k16.row.col.f32.bf16.bf16.f32 "
        "{%0,%1,%2,%3}, {%4,%5,%6,%7}, {%8,%9}, {%0,%1,%2,%3};"
        : "+f"(c[0]), "+f"(c[1]), "+f"(c[2]), "+f"(c[3])
        : "r"(a[0]), "r"(a[1]), "r"(a[2]), "r"(a[3]), "r"(b[0]), "r"(b[1]));
}

__device__ __forceinline__ float ftanh(float x) {
    float y;
    asm("tanh.approx.f32 %0, %1;" : "=f"(y) : "f"(x));
    return y;
}

// ---------------- scratch (static device globals; no allocations) ----------
__device__ float g_encproj[M_ENC * H_];      // [B*L, H]
__device__ float g_emb[T_ * B_ * D_];        // [t, b, d]
__device__ float g_ctx[B_ * F_];             // current context
__device__ float g_h[B_ * H_];
__device__ float g_c[B_ * H_];
__device__ float g_dec[B_ * H_];
__device__ float g_gpart[(size_t)KS_ * G4_ * B_]; // [s, gate, b]
// bf16 split operands
__device__ __nv_bfloat16 g_enc_hi[M_ENC * F_];
__device__ __nv_bfloat16 g_enc_lo[M_ENC * F_];
__device__ __nv_bfloat16 g_We_hi[H_ * F_];
__device__ __nv_bfloat16 g_We_lo[H_ * F_];
__device__ __nv_bfloat16 g_Wf_hi[(size_t)V_ * H_];
__device__ __nv_bfloat16 g_Wf_lo[(size_t)V_ * H_];
__device__ __nv_bfloat16 g_Hall_hi[M_FC * H_];
__device__ __nv_bfloat16 g_Hall_lo[M_FC * H_];
__device__ __nv_bfloat16 g_Wc_hi[(size_t)G4_ * KC_];  // [gate][k] cat(W_ih, W_hh)
__device__ __nv_bfloat16 g_Wc_lo[(size_t)G4_ * KC_];
// grid barrier (monotonic counter; persists across replays safely)
__device__ unsigned g_barArr = 0;

__device__ __forceinline__ void gridbar() {
    __syncthreads();
    if (threadIdx.x == 0) {
        __threadfence();
        unsigned my = atomicAdd(&g_barArr, 1u) + 1u;
        unsigned target = ((my + GRID_P - 1u) / GRID_P) * GRID_P;
        while (atomicAdd(&g_barArr, 0u) < target) __nanosleep(64);
        __threadfence();
    }
    __syncthreads();
}

// ---------------- fused preamble: all fp32->bf16 hi/lo splits --------------
#define PN0 (M_ENC * F_)                  // enc: 6,422,528
#define PN1 (H_ * F_)                     // We:    262,144
#define PN2 ((size_t)V_ * H_)             // Wf: 16,384,000
#define PN3 ((size_t)G4_ * KC_)           // Wc:  3,145,728
__global__ void k_prep(const float* __restrict__ enc, const float* __restrict__ We,
                       const float* __restrict__ Wf, const float* __restrict__ W_ih,
                       const float* __restrict__ W_hh) {
    size_t idx = (size_t)blockIdx.x * 256 + threadIdx.x;   // exact: 26,214,400
    float x;
    __nv_bfloat16 *hi, *lo;
    size_t off;
    if (idx < PN0) {
        off = idx; x = enc[off]; hi = g_enc_hi; lo = g_enc_lo;
    } else if (idx < PN0 + PN1) {
        off = idx - PN0; x = We[off]; hi = g_We_hi; lo = g_We_lo;
    } else if (idx < PN0 + PN1 + PN2) {
        off = idx - PN0 - PN1; x = Wf[off]; hi = g_Wf_hi; lo = g_Wf_lo;
    } else {
        off = idx - PN0 - PN1 - PN2;
        int m = (int)(off / KC_), k = (int)(off % KC_);
        x = (k < 1024) ? W_ih[(size_t)m * 1024 + k]
                       : W_hh[(size_t)m * 512 + (k - 1024)];
        hi = g_Wc_hi; lo = g_Wc_lo;
    }
    __nv_bfloat16 h = __float2bfloat16(x);
    hi[off] = h;
    lo[off] = __float2bfloat16(x - __bfloat162float(h));
}

// ---------------- init: zero h/c, gather embeddings ------------------------
__global__ void k_init(const int* __restrict__ captions,
                       const float* __restrict__ embedding) {
    int idx = blockIdx.x * 256 + threadIdx.x;      // T*B*D exact
    if (idx < B_ * H_) { g_h[idx] = 0.f; g_c[idx] = 0.f; }
    int t   = idx >> 15;
    int rem = idx & 32767;
    int b   = rem >> 9;
    int d   = rem & 511;
    int cap = captions[b * T_ + t];
    g_emb[idx] = embedding[(size_t)cap * D_ + d];
}

// ---------------- ctx0 = mean over L ---------------------------------------
__global__ void k_ctx0(const float* __restrict__ enc) {
    int idx = blockIdx.x * 256 + threadIdx.x;      // B*F exact
    int b = idx >> 9, f = idx & 511;
    const float* p = enc + ((size_t)b * L_) * F_ + f;
    float s = 0.f;
    for (int l = 0; l < L_; ++l) s += p[(size_t)l * F_];
    g_ctx[idx] = s * (1.0f / (float)L_);
}

// ---------------- big GEMM (tile 128x128) cp.async pipelined 3-pass --------
#define TILE_ELEM (128 * 72)
#define TILE_B    (TILE_ELEM * 2)
#define PIPE_SMEM (TILE_B * 8)          // 147456 bytes

__global__ __launch_bounds__(256) void k_mma128(
    const __nv_bfloat16* __restrict__ Ahi, const __nv_bfloat16* __restrict__ Alo,
    const __nv_bfloat16* __restrict__ Bhi, const __nv_bfloat16* __restrict__ Blo,
    const float* __restrict__ bias, float* __restrict__ out,
    int K, int ldc, int fc_remap)
{
    extern __shared__ char smem[];
    uint32_t sb = smem_to_u32(smem);
    int tid = threadIdx.x, wid = tid >> 5, lane = tid & 31;
    int m0 = blockIdx.x * 128, n0 = blockIdx.y * 128;
    int warp_m = wid & 1, warp_n = wid >> 1;

    float acc[4][4][4];
#pragma unroll
    for (int i = 0; i < 4; i++)
#pragma unroll
        for (int j = 0; j < 4; j++)
#pragma unroll
            for (int r = 0; r < 4; r++) acc[i][j][r] = 0.f;

    int row_ld = tid >> 1, q_ld = tid & 1;
    int sub = lane >> 3, ri = lane & 7;
    uint32_t aoff = (uint32_t)((((sub & 1) * 8 + ri) * 72 + (sub >> 1) * 8) * 2)
                  + (uint32_t)(warp_m * 64 * 144);
    uint32_t boff = (uint32_t)((((sub >> 1) * 8 + ri) * 72 + (sub & 1) * 8) * 2)
                  + (uint32_t)(warp_n * 32 * 144);

    int NC = K >> 6;

#define ISSUE(c, s) do { \
        int k0 = (c) << 6; \
        uint32_t st = sb + (uint32_t)((s) * 4 * TILE_B); \
        size_t gA = (size_t)(m0 + row_ld) * K + k0 + q_ld * 32; \
        size_t gB = (size_t)(n0 + row_ld) * K + k0 + q_ld * 32; \
        uint32_t so = (uint32_t)((row_ld * 72 + q_ld * 32) * 2); \
        _Pragma("unroll") \
        for (int qq = 0; qq < 4; ++qq) { \
            CP16(st + 0 * TILE_B + so + qq * 16, Ahi + gA + qq * 8); \
            CP16(st + 1 * TILE_B + so + qq * 16, Alo + gA + qq * 8); \
            CP16(st + 2 * TILE_B + so + qq * 16, Bhi + gB + qq * 8); \
            CP16(st + 3 * TILE_B + so + qq * 16, Blo + gB + qq * 8); \
        } \
        CP_COMMIT(); \
    } while (0)

    ISSUE(0, 0);
    for (int c = 0; c < NC; ++c) {
        int s = c & 1;
        if (c + 1 < NC) { ISSUE(c + 1, (c + 1) & 1); CP_WAIT(1); }
        else           { CP_WAIT(0); }
        __syncthreads();
        uint32_t bAh = sb + (uint32_t)(s * 4 * TILE_B) + aoff;
        uint32_t bAl = bAh + TILE_B;
        uint32_t bBh = sb + (uint32_t)(s * 4 * TILE_B + 2 * TILE_B) + boff;
        uint32_t bBl = bBh + TILE_B;
#pragma unroll
        for (int ks = 0; ks < 64; ks += 16) {
            uint32_t ah[4][4], al[4][4], bh[4][2], bl[4][2];
#pragma unroll
            for (int mi = 0; mi < 4; ++mi) {
                LDMX4(ah[mi][0], ah[mi][1], ah[mi][2], ah[mi][3],
                      bAh + (uint32_t)(mi * 16 * 144 + ks * 2));
                LDMX4(al[mi][0], al[mi][1], al[mi][2], al[mi][3],
                      bAl + (uint32_t)(mi * 16 * 144 + ks * 2));
            }
            LDMX4(bh[0][0], bh[0][1], bh[1][0], bh[1][1], bBh + (uint32_t)(ks * 2));
            LDMX4(bh[2][0], bh[2][1], bh[3][0], bh[3][1], bBh + (uint32_t)(16 * 144 + ks * 2));
            LDMX4(bl[0][0], bl[0][1], bl[1][0], bl[1][1], bBl + (uint32_t)(ks * 2));
            LDMX4(bl[2][0], bl[2][1], bl[3][0], bl[3][1], bBl + (uint32_t)(16 * 144 + ks * 2));
#pragma unroll
            for (int mi = 0; mi < 4; ++mi)
#pragma unroll
                for (int ni = 0; ni < 4; ++ni) {
                    mma_bf16(acc[mi][ni], ah[mi], bh[ni]);
                    mma_bf16(acc[mi][ni], ah[mi], bl[ni]);
                    mma_bf16(acc[mi][ni], al[mi], bh[ni]);
                }
        }
        __syncthreads();
    }
#undef ISSUE

    int g = lane >> 2, t4 = lane & 3;
    float2 bv[4];
#pragma unroll
    for (int ni = 0; ni < 4; ++ni)
        bv[ni] = *(const float2*)(bias + n0 + warp_n * 32 + ni * 8 + 2 * t4);
#pragma unroll
    for (int mi = 0; mi < 4; ++mi)
#pragma unroll
        for (int rr = 0; rr < 2; ++rr) {
            int m = m0 + warp_m * 64 + mi * 16 + rr * 8 + g;
            int row = fc_remap ? ((m & 63) * T_ + (m >> 6)) : m;
            float* po = out + (size_t)row * ldc + n0 + warp_n * 32 + 2 * t4;
#pragma unroll
            for (int ni = 0; ni < 4; ++ni) {
                float2 v;
                v.x = acc[mi][ni][rr * 2 + 0] + bv[ni].x;
                v.y = acc[mi][ni][rr * 2 + 1] + bv[ni].y;
                *(float2*)(po + ni * 8) = v;
            }
        }
}

// ---------------- persistent fused recurrence kernel ------------------------
__global__ __launch_bounds__(256, 1) void k_loop(
    const float* __restrict__ enc, const float* __restrict__ Wd,
    const float* __restrict__ bd, const float* __restrict__ vw,
    const float* __restrict__ vb, const float* __restrict__ b_ih,
    const float* __restrict__ b_hh)
{
    __shared__ union {
        struct { float hs[64][65]; float ws[4][64]; } dec;
        struct { float dec_s[512]; float vw_s[512]; float sc[200]; float sred[256]; } at;
        struct { __nv_bfloat16 As[2][128 * 40]; __nv_bfloat16 Bs[2][64 * 40]; } gm;
    } sm;

    int cta = blockIdx.x;
    int tid = threadIdx.x, wid = tid >> 5, lane = tid & 31;

    // gates-gemm constants for this CTA
    int gm_m0 = (cta >> 3) * 128;
    int gm_sp = cta & 7;
    int warp_m = wid >> 1, warp_n = wid & 1;
    int sub = lane >> 3, ri = lane & 7;
    uint32_t aoff_g = (uint32_t)((((sub & 1) * 8 + ri) * 40 + (sub >> 1) * 8) * 2);
    uint32_t boff_g = (uint32_t)((((sub >> 1) * 8 + ri) * 40 + (sub & 1) * 8) * 2);
    uint32_t aAh = smem_to_u32(&sm.gm.As[0][0]) + (uint32_t)(warp_m * 32 * 40 * 2) + aoff_g;
    uint32_t aAl = smem_to_u32(&sm.gm.As[1][0]) + (uint32_t)(warp_m * 32 * 40 * 2) + aoff_g;
    uint32_t aBh = smem_to_u32(&sm.gm.Bs[0][0]) + (uint32_t)(warp_n * 32 * 40 * 2) + boff_g;
    uint32_t aBl = smem_to_u32(&sm.gm.Bs[1][0]) + (uint32_t)(warp_n * 32 * 40 * 2) + boff_g;

    for (int t = 0; t < T_; ++t) {
        if (t > 0) {
            // ---- dec phase: cta computes dec[:, cta*4 .. cta*4+3] ----
            {
                int n0 = cta * 4;
                int bq = tid & 63, jj = tid >> 6;
                float acc = 0.f;
                for (int kb = 0; kb < 512; kb += 64) {
#pragma unroll
                    for (int it = 0; it < 4; ++it) {
                        int r = (tid >> 4) + it * 16;
                        int kk = (tid & 15) * 4;
                        float4 v = *(const float4*)(g_h + (size_t)r * 512 + kb + kk);
                        sm.dec.hs[r][kk+0]=v.x; sm.dec.hs[r][kk+1]=v.y;
                        sm.dec.hs[r][kk+2]=v.z; sm.dec.hs[r][kk+3]=v.w;
                    }
                    if (tid < 64) {
                        int n = tid >> 4, kk = (tid & 15) * 4;
                        float4 v = *(const float4*)(Wd + (size_t)(n0 + n) * 512 + kb + kk);
                        sm.dec.ws[n][kk+0]=v.x; sm.dec.ws[n][kk+1]=v.y;
                        sm.dec.ws[n][kk+2]=v.z; sm.dec.ws[n][kk+3]=v.w;
                    }
                    __syncthreads();
#pragma unroll
                    for (int k = 0; k < 64; ++k)
                        acc += sm.dec.hs[bq][k] * sm.dec.ws[jj][k];
                    __syncthreads();
                }
                g_dec[(size_t)bq * 512 + n0 + jj] = acc + bd[n0 + jj];
            }
            gridbar();

            // ---- attention phase: cta < 64, b = cta ----
            if (cta < 64) {
                int b = cta;
                for (int i = tid; i < 512; i += 256) {
                    sm.at.dec_s[i] = g_dec[(size_t)b * 512 + i];
                    sm.at.vw_s[i]  = vw[i];
                }
                __syncthreads();
                float v_b = vb[0];
                for (int l = wid; l < L_; l += 8) {
                    const float* ep = g_encproj + ((size_t)(b * L_ + l)) * 512;
                    float s = 0.f;
                    for (int hh = lane; hh < 512; hh += 32)
                        s += ftanh(ep[hh] + sm.at.dec_s[hh]) * sm.at.vw_s[hh];
#pragma unroll
                    for (int off = 16; off; off >>= 1) s += __shfl_xor_sync(0xffffffffu, s, off);
                    if (lane == 0) sm.at.sc[l] = s + v_b;
                }
                __syncthreads();
                float mv = (tid < L_) ? sm.at.sc[tid] : -1e30f;
                sm.at.sred[tid] = mv; __syncthreads();
                for (int s = 128; s; s >>= 1) {
                    if (tid < s) sm.at.sred[tid] = fmaxf(sm.at.sred[tid], sm.at.sred[tid + s]);
                    __syncthreads();
                }
                float mx = sm.at.sred[0]; __syncthreads();
                float ev = (tid < L_) ? __expf(sm.at.sc[tid] - mx) : 0.f;
                sm.at.sred[tid] = ev; __syncthreads();
                for (int s = 128; s; s >>= 1) {
                    if (tid < s) sm.at.sred[tid] += sm.at.sred[tid + s];
                    __syncthreads();
                }
                float inv = 1.0f / sm.at.sred[0]; __syncthreads();
                if (tid < L_) sm.at.sc[tid] = ev * inv;
                __syncthreads();
                for (int f = tid; f < F_; f += 256) {
                    const float* eb = enc + ((size_t)b * L_) * F_ + f;
                    float a = 0.f;
                    for (int l = 0; l < L_; ++l) a += sm.at.sc[l] * eb[(size_t)l * F_];
                    g_ctx[(size_t)b * F_ + f] = a;
                }
            }
            gridbar();
        }

        // ---- gates GEMM phase: m-tile = cta>>3, K-split = cta&7 ----
        {
            float acc[2][4][4];
#pragma unroll
            for (int i = 0; i < 2; i++)
#pragma unroll
                for (int j = 0; j < 4; j++)
#pragma unroll
                    for (int r = 0; r < 4; r++) acc[i][j][r] = 0.f;

            const float* embt = g_emb + (size_t)t * B_ * 512;
            int kbeg = gm_sp * (KC_ / KS_);
            for (int k0 = kbeg; k0 < kbeg + KC_ / KS_; k0 += 32) {
#pragma unroll
                for (int i = 0; i < 2; ++i) {
                    int idx = tid + i * 256;
                    int row = idx >> 2, q = idx & 3;
                    int s = row * 40 + q * 8;
                    size_t ga = (size_t)(gm_m0 + row) * KC_ + k0 + q * 8;
                    *(uint4*)&sm.gm.As[0][s] = *(const uint4*)(g_Wc_hi + ga);
                    *(uint4*)&sm.gm.As[1][s] = *(const uint4*)(g_Wc_lo + ga);
                }
#pragma unroll
                for (int i = 0; i < 2; ++i) {
                    int idx = tid + i * 256;
                    int row = idx >> 3, q = idx & 7;
                    int kk = k0 + q * 4;
                    const float* src = (kk < 512)  ? (embt  + (size_t)row * 512 + kk)
                                     : (kk < 1024) ? (g_ctx + (size_t)row * 512 + kk - 512)
                                                   : (g_h   + (size_t)row * 512 + kk - 1024);
                    float4 v = *(const float4*)src;
                    __nv_bfloat16 hx = __float2bfloat16(v.x), hy = __float2bfloat16(v.y);
                    __nv_bfloat16 hz = __float2bfloat16(v.z), hw = __float2bfloat16(v.w);
                    int s = row * 40 + q * 4;
                    sm.gm.Bs[0][s+0]=hx; sm.gm.Bs[0][s+1]=hy;
                    sm.gm.Bs[0][s+2]=hz; sm.gm.Bs[0][s+3]=hw;
                    sm.gm.Bs[1][s+0]=__float2bfloat16(v.x - __bfloat162float(hx));
                    sm.gm.Bs[1][s+1]=__float2bfloat16(v.y - __bfloat162float(hy));
                    sm.gm.Bs[1][s+2]=__float2bfloat16(v.z - __bfloat162float(hz));
                    sm.gm.Bs[1][s+3]=__float2bfloat16(v.w - __bfloat162float(hw));
                }
                __syncthreads();
#pragma unroll
                for (int ks = 0; ks < 32; ks += 16) {
                    uint32_t ah[2][4], al[2][4], bh[4][2], bl[4][2];
#pragma unroll
                    for (int mi = 0; mi < 2; ++mi) {
                        LDMX4(ah[mi][0], ah[mi][1], ah[mi][2], ah[mi][3],
                              aAh + (uint32_t)((mi * 16 * 40 + ks) * 2));
                        LDMX4(al[mi][0], al[mi][1], al[mi][2], al[mi][3],
                              aAl + (uint32_t)((mi * 16 * 40 + ks) * 2));
                    }
                    LDMX4(bh[0][0], bh[0][1], bh[1][0], bh[1][1], aBh + (uint32_t)(ks * 2));
                    LDMX4(bh[2][0], bh[2][1], bh[3][0], bh[3][1], aBh + (uint32_t)((16 * 40 + ks) * 2));
                    LDMX4(bl[0][0], bl[0][1], bl[1][0], bl[1][1], aBl + (uint32_t)(ks * 2));
                    LDMX4(bl[2][0], bl[2][1], bl[3][0], bl[3][1], aBl + (uint32_t)((16 * 40 + ks) * 2));
#pragma unroll
                    for (int mi = 0; mi < 2; ++mi)
#pragma unroll
                        for (int ni = 0; ni < 4; ++ni) {
                            mma_bf16(acc[mi][ni], ah[mi], bh[ni]);
                            mma_bf16(acc[mi][ni], ah[mi], bl[ni]);
                            mma_bf16(acc[mi][ni], al[mi], bh[ni]);
                        }
                }
                __syncthreads();
            }

            float* base = g_gpart + (size_t)gm_sp * G4_ * 64;
            int g = lane >> 2, t4 = lane & 3;
#pragma unroll
            for (int mi = 0; mi < 2; ++mi)
#pragma unroll
                for (int rr = 0; rr < 2; ++rr) {
                    int m = gm_m0 + warp_m * 32 + mi * 16 + rr * 8 + g;
                    float* po = base + (size_t)m * 64 + warp_n * 32 + 2 * t4;
#pragma unroll
                    for (int ni = 0; ni < 4; ++ni) {
                        float2 v;
                        v.x = acc[mi][ni][rr * 2 + 0];
                        v.y = acc[mi][ni][rr * 2 + 1];
                        *(float2*)(po + ni * 8) = v;
                    }
                }
        }
        gridbar();

        // ---- pointwise phase: idx over B*H = 32768 = 128*256 ----
        {
            int idx = cta * 256 + tid;
            int b = idx & 63, h = idx >> 6;
            float gi = b_ih[h]        + b_hh[h];
            float gf = b_ih[h + 512]  + b_hh[h + 512];
            float gg = b_ih[h + 1024] + b_hh[h + 1024];
            float go = b_ih[h + 1536] + b_hh[h + 1536];
#pragma unroll
            for (int s = 0; s < KS_; ++s) {
                const float* p = g_gpart + (size_t)s * G4_ * 64;
                gi += p[(size_t)(h)        * 64 + b];
                gf += p[(size_t)(h + 512)  * 64 + b];
                gg += p[(size_t)(h + 1024) * 64 + b];
                go += p[(size_t)(h + 1536) * 64 + b];
            }
            float c  = g_c[(size_t)b * 512 + h];
            float si = 1.f / (1.f + expf(-gi));
            float sf = 1.f / (1.f + expf(-gf));
            float so = 1.f / (1.f + expf(-go));
            float c2 = sf * c + si * tanhf(gg);
            float h2 = so * tanhf(c2);
            g_c[(size_t)b * 512 + h] = c2;
            g_h[(size_t)b * 512 + h] = h2;
            size_t mrow = ((size_t)t * 64 + b) * 512 + h;
            __nv_bfloat16 hh = __float2bfloat16(h2);
            g_Hall_hi[mrow] = hh;
            g_Hall_lo[mrow] = __float2bfloat16(h2 - __bfloat162float(hh));
        }
        gridbar();
    }
}

// ---------------- launch ----------------------------------------------------
extern "C" void kernel_launch(void* const* d_in, const int* in_sizes, int n_in,
                              void* d_out, int out_size) {
    const float* enc  = (const float*)d_in[0];
    const int*   caps = (const int*)  d_in[1];
    const float* emb  = (const float*)d_in[2];
    const float* We   = (const float*)d_in[3];
    const float* be   = (const float*)d_in[4];
    const float* Wd   = (const float*)d_in[5];
    const float* bd   = (const float*)d_in[6];
    const float* vw   = (const float*)d_in[7];
    const float* vb   = (const float*)d_in[8];
    const float* W_ih = (const float*)d_in[9];
    const float* W_hh = (const float*)d_in[10];
    const float* b_ih = (const float*)d_in[11];
    const float* b_hh = (const float*)d_in[12];
    const float* Wf   = (const float*)d_in[13];
    const float* bf   = (const float*)d_in[14];
    float* out = (float*)d_out;

    cudaFuncSetAttribute(k_mma128, cudaFuncAttributeMaxDynamicSharedMemorySize, PIPE_SMEM);

    void *p_enc_hi, *p_enc_lo, *p_We_hi, *p_We_lo, *p_Wf_hi, *p_Wf_lo,
         *p_Hall_hi, *p_Hall_lo, *p_encproj;
    cudaGetSymbolAddress(&p_enc_hi, g_enc_hi);
    cudaGetSymbolAddress(&p_enc_lo, g_enc_lo);
    cudaGetSymbolAddress(&p_We_hi, g_We_hi);
    cudaGetSymbolAddress(&p_We_lo, g_We_lo);
    cudaGetSymbolAddress(&p_Wf_hi, g_Wf_hi);
    cudaGetSymbolAddress(&p_Wf_lo, g_Wf_lo);
    cudaGetSymbolAddress(&p_Hall_hi, g_Hall_hi);
    cudaGetSymbolAddress(&p_Hall_lo, g_Hall_lo);
    cudaGetSymbolAddress(&p_encproj, g_encproj);

    k_init<<<(T_ * B_ * D_) / 256, 256>>>(caps, emb);
    k_ctx0<<<(B_ * F_) / 256, 256>>>(enc);
    k_prep<<<(int)((PN0 + PN1 + PN2 + PN3) / 256), 256>>>(enc, We, Wf, W_ih, W_hh);

    // enc_proj = enc @ We^T + be
    k_mma128<<<dim3(M_ENC / 128, H_ / 128), 256, PIPE_SMEM>>>(
        (const __nv_bfloat16*)p_enc_hi, (const __nv_bfloat16*)p_enc_lo,
        (const __nv_bfloat16*)p_We_hi, (const __nv_bfloat16*)p_We_lo,
        be, (float*)p_encproj, F_, H_, 0);

    // entire 32-step recurrence in one persistent kernel
    k_loop<<<GRID_P, 256>>>(enc, Wd, bd, vw, vb, b_ih, b_hh);

    // fc logits: Hall @ Wf^T + bf
    k_mma128<<<dim3(M_FC / 128, V_ / 128), 256, PIPE_SMEM>>>(
        (const __nv_bfloat16*)p_Hall_hi, (const __nv_bfloat16*)p_Hall_lo,
        (const __nv_bfloat16*)p_Wf_hi, (const __nv_bfloat16*)p_Wf_lo,
        bf, out, H_, V_, 1);
}

// round 6
// speedup vs baseline: 1.7767x; 1.0821x over previous
#include <cuda_runtime.h>
#include <cuda_bf16.h>
#include <math.h>
#include <stdint.h>

// Problem constants
#define B_  64
#define L_  196
#define F_  512
#define T_  32
#define H_  512
#define D_  512
#define V_  32000
#define G4_ 2048               // 4*H
#define M_ENC (B_*L_)          // 12544
#define M_FC  (T_*B_)          // 2048
#define KS_ 8                  // K-splits for LSTM gates GEMM
#define KC_ 1536               // D+F+H
#define GRID_P 128             // persistent-loop grid (must be <= #SMs)

// ====================== warp-mma helpers (sm_80 baseline ISA) ==============
__device__ __forceinline__ uint32_t smem_to_u32(const void* p) {
    uint32_t a;
    asm("{ .reg .u64 t; cvta.to.shared.u64 t, %1; cvt.u32.u64 %0, t; }" : "=r"(a) : "l"(p));
    return a;
}

#define LDMX4(r0,r1,r2,r3,addr) \
    asm volatile("ldmatrix.sync.aligned.m8n8.x4.shared.b16 {%0,%1,%2,%3}, [%4];" \
        : "=r"(r0),"=r"(r1),"=r"(r2),"=r"(r3) : "r"(addr))

#define CP16(dst, src) \
    asm volatile("cp.async.cg.shared.global [%0], [%1], 16;" :: "r"(dst), "l"(src))
#define CP_COMMIT() asm volatile("cp.async.commit_group;")
#define CP_WAIT(n)  asm volatile("cp.async.wait_group %0;" :: "n"(n))

__device__ __forceinline__ void mma_bf16(float* c, const uint32_t* a, const uint32_t* b) {
    asm volatile(
        "mma.sync.aligned.m16n8k16.row.col.f32.bf16.bf16.f32 "
        "{%0,%1,%2,%3}, {%4,%5,%6,%7}, {%8,%9}, {%0,%1,%2,%3};"
        : "+f"(c[0]), "+f"(c[1]), "+f"(c[2]), "+f"(c[3])
        : "r"(a[0]), "r"(a[1]), "r"(a[2]), "r"(a[3]), "r"(b[0]), "r"(b[1]));
}

__device__ __forceinline__ float ftanh(float x) {
    float y;
    asm("tanh.approx.f32 %0, %1;" : "=f"(y) : "f"(x));
    return y;
}

// ---------------- scratch (static device globals; no allocations) ----------
__device__ float g_encproj[M_ENC * H_];      // [B*L, H]
__device__ float g_emb[T_ * B_ * D_];        // [t, b, d]
__device__ float g_ctx[B_ * F_];             // current context
__device__ float g_h[B_ * H_];
__device__ float g_c[B_ * H_];
__device__ float g_dec[B_ * H_];
__device__ float g_gpart[(size_t)KS_ * G4_ * B_]; // [s, gate, b]
// bf16 split operands
__device__ __nv_bfloat16 g_enc_hi[M_ENC * F_];
__device__ __nv_bfloat16 g_enc_lo[M_ENC * F_];
__device__ __nv_bfloat16 g_We_hi[H_ * F_];
__device__ __nv_bfloat16 g_We_lo[H_ * F_];
__device__ __nv_bfloat16 g_Wf_hi[(size_t)V_ * H_];
__device__ __nv_bfloat16 g_Wf_lo[(size_t)V_ * H_];
__device__ __nv_bfloat16 g_Hall_hi[M_FC * H_];
__device__ __nv_bfloat16 g_Hall_lo[M_FC * H_];
__device__ __nv_bfloat16 g_Wc_hi[(size_t)G4_ * KC_];  // [gate][k] cat(W_ih, W_hh)
__device__ __nv_bfloat16 g_Wc_lo[(size_t)G4_ * KC_];
// grid barrier (monotonic counter; persists across replays safely)
__device__ unsigned g_barArr = 0;

__device__ __forceinline__ void gridbar() {
    __syncthreads();
    if (threadIdx.x == 0) {
        unsigned my;
        asm volatile("atom.global.release.gpu.add.u32 %0, [%1], 1;"
                     : "=r"(my) : "l"(&g_barArr) : "memory");
        my += 1u;
        unsigned target = ((my + GRID_P - 1u) / GRID_P) * GRID_P;
        unsigned v;
        do {
            asm volatile("ld.global.acquire.gpu.u32 %0, [%1];"
                         : "=r"(v) : "l"(&g_barArr) : "memory");
        } while (v < target);
    }
    __syncthreads();
}

// ---------------- fused preamble: all fp32->bf16 hi/lo splits --------------
#define PN0 (M_ENC * F_)                  // enc: 6,422,528
#define PN1 (H_ * F_)                     // We:    262,144
#define PN2 ((size_t)V_ * H_)             // Wf: 16,384,000
#define PN3 ((size_t)G4_ * KC_)           // Wc:  3,145,728
__global__ void k_prep(const float* __restrict__ enc, const float* __restrict__ We,
                       const float* __restrict__ Wf, const float* __restrict__ W_ih,
                       const float* __restrict__ W_hh) {
    size_t idx = (size_t)blockIdx.x * 256 + threadIdx.x;   // exact: 26,214,400
    float x;
    __nv_bfloat16 *hi, *lo;
    size_t off;
    if (idx < PN0) {
        off = idx; x = enc[off]; hi = g_enc_hi; lo = g_enc_lo;
    } else if (idx < PN0 + PN1) {
        off = idx - PN0; x = We[off]; hi = g_We_hi; lo = g_We_lo;
    } else if (idx < PN0 + PN1 + PN2) {
        off = idx - PN0 - PN1; x = Wf[off]; hi = g_Wf_hi; lo = g_Wf_lo;
    } else {
        off = idx - PN0 - PN1 - PN2;
        int m = (int)(off / KC_), k = (int)(off % KC_);
        x = (k < 1024) ? W_ih[(size_t)m * 1024 + k]
                       : W_hh[(size_t)m * 512 + (k - 1024)];
        hi = g_Wc_hi; lo = g_Wc_lo;
    }
    __nv_bfloat16 h = __float2bfloat16(x);
    hi[off] = h;
    lo[off] = __float2bfloat16(x - __bfloat162float(h));
}

// ---------------- init: zero h/c, gather embeddings ------------------------
__global__ void k_init(const int* __restrict__ captions,
                       const float* __restrict__ embedding) {
    int idx = blockIdx.x * 256 + threadIdx.x;      // T*B*D exact
    if (idx < B_ * H_) { g_h[idx] = 0.f; g_c[idx] = 0.f; }
    int t   = idx >> 15;
    int rem = idx & 32767;
    int b   = rem >> 9;
    int d   = rem & 511;
    int cap = captions[b * T_ + t];
    g_emb[idx] = embedding[(size_t)cap * D_ + d];
}

// ---------------- ctx0 = mean over L ---------------------------------------
__global__ void k_ctx0(const float* __restrict__ enc) {
    int idx = blockIdx.x * 256 + threadIdx.x;      // B*F exact
    int b = idx >> 9, f = idx & 511;
    const float* p = enc + ((size_t)b * L_) * F_ + f;
    float s = 0.f;
    for (int l = 0; l < L_; ++l) s += p[(size_t)l * F_];
    g_ctx[idx] = s * (1.0f / (float)L_);
}

// ---------------- big GEMM (tile 128x128) cp.async pipelined 3-pass --------
// K-chunk 32, double-buffered -> 81920 B smem -> 2 CTAs/SM
#define T32  (128 * 40)                 // tile elems: 128 rows x 32 cols + 8 pad
#define T32B (T32 * 2)                  // 10240 bytes
#define PIPE_SMEM (T32B * 8)            // 2 stages x 4 tiles = 81920 bytes

__global__ __launch_bounds__(256, 2) void k_mma128(
    const __nv_bfloat16* __restrict__ Ahi, const __nv_bfloat16* __restrict__ Alo,
    const __nv_bfloat16* __restrict__ Bhi, const __nv_bfloat16* __restrict__ Blo,
    const float* __restrict__ bias, float* __restrict__ out,
    int K, int ldc, int fc_remap)
{
    extern __shared__ char smem[];
    uint32_t sb = smem_to_u32(smem);
    int tid = threadIdx.x, wid = tid >> 5, lane = tid & 31;
    int m0 = blockIdx.x * 128, n0 = blockIdx.y * 128;
    int warp_m = wid & 1, warp_n = wid >> 1;   // 2 x 4 warp grid, warp tile 64x32

    float acc[4][4][4];
#pragma unroll
    for (int i = 0; i < 4; i++)
#pragma unroll
        for (int j = 0; j < 4; j++)
#pragma unroll
            for (int r = 0; r < 4; r++) acc[i][j][r] = 0.f;

    int row_ld = tid >> 1, q_ld = tid & 1;        // each thread: 32B per tile
    uint32_t so_ld = (uint32_t)(row_ld * 80 + q_ld * 32);
    int sub = lane >> 3, ri = lane & 7;
    uint32_t aoff = (uint32_t)((((sub & 1) * 8 + ri) * 40 + (sub >> 1) * 8) * 2)
                  + (uint32_t)(warp_m * 64 * 80);
    uint32_t boff = (uint32_t)((((sub >> 1) * 8 + ri) * 40 + (sub & 1) * 8) * 2)
                  + (uint32_t)(warp_n * 32 * 80);

    int NC = K >> 5;

#define ISSUE(c, s) do { \
        int k0 = (c) << 5; \
        uint32_t st = sb + (uint32_t)((s) * 4 * T32B); \
        size_t gA = (size_t)(m0 + row_ld) * K + k0 + q_ld * 16; \
        size_t gB = (size_t)(n0 + row_ld) * K + k0 + q_ld * 16; \
        CP16(st + 0 * T32B + so_ld,      Ahi + gA); \
        CP16(st + 0 * T32B + so_ld + 16, Ahi + gA + 8); \
        CP16(st + 1 * T32B + so_ld,      Alo + gA); \
        CP16(st + 1 * T32B + so_ld + 16, Alo + gA + 8); \
        CP16(st + 2 * T32B + so_ld,      Bhi + gB); \
        CP16(st + 2 * T32B + so_ld + 16, Bhi + gB + 8); \
        CP16(st + 3 * T32B + so_ld,      Blo + gB); \
        CP16(st + 3 * T32B + so_ld + 16, Blo + gB + 8); \
        CP_COMMIT(); \
    } while (0)

    ISSUE(0, 0);
    for (int c = 0; c < NC; ++c) {
        int s = c & 1;
        if (c + 1 < NC) { ISSUE(c + 1, (c + 1) & 1); CP_WAIT(1); }
        else           { CP_WAIT(0); }
        __syncthreads();
        uint32_t bAh = sb + (uint32_t)(s * 4 * T32B) + aoff;
        uint32_t bAl = bAh + T32B;
        uint32_t bBh = sb + (uint32_t)(s * 4 * T32B + 2 * T32B) + boff;
        uint32_t bBl = bBh + T32B;
#pragma unroll
        for (int ks = 0; ks < 32; ks += 16) {
            uint32_t ah[4][4], al[4][4], bh[4][2], bl[4][2];
#pragma unroll
            for (int mi = 0; mi < 4; ++mi) {
                LDMX4(ah[mi][0], ah[mi][1], ah[mi][2], ah[mi][3],
                      bAh + (uint32_t)(mi * 16 * 80 + ks * 2));
                LDMX4(al[mi][0], al[mi][1], al[mi][2], al[mi][3],
                      bAl + (uint32_t)(mi * 16 * 80 + ks * 2));
            }
            LDMX4(bh[0][0], bh[0][1], bh[1][0], bh[1][1], bBh + (uint32_t)(ks * 2));
            LDMX4(bh[2][0], bh[2][1], bh[3][0], bh[3][1], bBh + (uint32_t)(16 * 80 + ks * 2));
            LDMX4(bl[0][0], bl[0][1], bl[1][0], bl[1][1], bBl + (uint32_t)(ks * 2));
            LDMX4(bl[2][0], bl[2][1], bl[3][0], bl[3][1], bBl + (uint32_t)(16 * 80 + ks * 2));
#pragma unroll
            for (int mi = 0; mi < 4; ++mi)
#pragma unroll
                for (int ni = 0; ni < 4; ++ni) {
                    mma_bf16(acc[mi][ni], ah[mi], bh[ni]);
                    mma_bf16(acc[mi][ni], ah[mi], bl[ni]);
                    mma_bf16(acc[mi][ni], al[mi], bh[ni]);
                }
        }
        __syncthreads();
    }
#undef ISSUE

    int g = lane >> 2, t4 = lane & 3;
    float2 bv[4];
#pragma unroll
    for (int ni = 0; ni < 4; ++ni)
        bv[ni] = *(const float2*)(bias + n0 + warp_n * 32 + ni * 8 + 2 * t4);
#pragma unroll
    for (int mi = 0; mi < 4; ++mi)
#pragma unroll
        for (int rr = 0; rr < 2; ++rr) {
            int m = m0 + warp_m * 64 + mi * 16 + rr * 8 + g;
            int row = fc_remap ? ((m & 63) * T_ + (m >> 6)) : m;
            float* po = out + (size_t)row * ldc + n0 + warp_n * 32 + 2 * t4;
#pragma unroll
            for (int ni = 0; ni < 4; ++ni) {
                float2 v;
                v.x = acc[mi][ni][rr * 2 + 0] + bv[ni].x;
                v.y = acc[mi][ni][rr * 2 + 1] + bv[ni].y;
                *(float2*)(po + ni * 8) = v;
            }
        }
}

// ---------------- persistent fused recurrence kernel ------------------------
__global__ __launch_bounds__(256, 1) void k_loop(
    const float* __restrict__ enc, const float* __restrict__ Wd,
    const float* __restrict__ bd, const float* __restrict__ vw,
    const float* __restrict__ vb, const float* __restrict__ b_ih,
    const float* __restrict__ b_hh)
{
    __shared__ union {
        struct { float hs[64][65]; float ws[4][64]; } dec;
        struct { float dec_s[512]; float vw_s[512]; float sc[200];
                 float sred[256]; float red2[8][512]; } at;
        struct { __nv_bfloat16 As[2][128 * 40]; __nv_bfloat16 Bs[2][64 * 40]; } gm;
    } sm;

    int cta = blockIdx.x;
    int tid = threadIdx.x, wid = tid >> 5, lane = tid & 31;

    // gates-gemm constants for this CTA
    int gm_m0 = (cta >> 3) * 128;
    int gm_sp = cta & 7;
    int warp_m = wid >> 1, warp_n = wid & 1;
    int sub = lane >> 3, ri = lane & 7;
    uint32_t aoff_g = (uint32_t)((((sub & 1) * 8 + ri) * 40 + (sub >> 1) * 8) * 2);
    uint32_t boff_g = (uint32_t)((((sub >> 1) * 8 + ri) * 40 + (sub & 1) * 8) * 2);
    uint32_t aAh = smem_to_u32(&sm.gm.As[0][0]) + (uint32_t)(warp_m * 32 * 40 * 2) + aoff_g;
    uint32_t aAl = smem_to_u32(&sm.gm.As[1][0]) + (uint32_t)(warp_m * 32 * 40 * 2) + aoff_g;
    uint32_t aBh = smem_to_u32(&sm.gm.Bs[0][0]) + (uint32_t)(warp_n * 32 * 40 * 2) + boff_g;
    uint32_t aBl = smem_to_u32(&sm.gm.Bs[1][0]) + (uint32_t)(warp_n * 32 * 40 * 2) + boff_g;

    for (int t = 0; t < T_; ++t) {
        if (t > 0) {
            // ---- dec phase: cta computes dec[:, cta*4 .. cta*4+3] ----
            {
                int n0 = cta * 4;
                int bq = tid & 63, jj = tid >> 6;
                float acc = 0.f;
                for (int kb = 0; kb < 512; kb += 64) {
#pragma unroll
                    for (int it = 0; it < 4; ++it) {
                        int r = (tid >> 4) + it * 16;
                        int kk = (tid & 15) * 4;
                        float4 v = *(const float4*)(g_h + (size_t)r * 512 + kb + kk);
                        sm.dec.hs[r][kk+0]=v.x; sm.dec.hs[r][kk+1]=v.y;
                        sm.dec.hs[r][kk+2]=v.z; sm.dec.hs[r][kk+3]=v.w;
                    }
                    if (tid < 64) {
                        int n = tid >> 4, kk = (tid & 15) * 4;
                        float4 v = *(const float4*)(Wd + (size_t)(n0 + n) * 512 + kb + kk);
                        sm.dec.ws[n][kk+0]=v.x; sm.dec.ws[n][kk+1]=v.y;
                        sm.dec.ws[n][kk+2]=v.z; sm.dec.ws[n][kk+3]=v.w;
                    }
                    __syncthreads();
#pragma unroll
                    for (int k = 0; k < 64; ++k)
                        acc += sm.dec.hs[bq][k] * sm.dec.ws[jj][k];
                    __syncthreads();
                }
                g_dec[(size_t)bq * 512 + n0 + jj] = acc + bd[n0 + jj];
            }
            gridbar();

            // ---- attention phase: cta < 64, b = cta ----
            if (cta < 64) {
                int b = cta;
                for (int i = tid; i < 512; i += 256) {
                    sm.at.dec_s[i] = g_dec[(size_t)b * 512 + i];
                    sm.at.vw_s[i]  = vw[i];
                }
                __syncthreads();
                float v_b = vb[0];
                for (int l = wid; l < L_; l += 8) {
                    const float* ep = g_encproj + ((size_t)(b * L_ + l)) * 512;
                    float s = 0.f;
                    for (int hh = lane; hh < 512; hh += 32)
                        s += ftanh(ep[hh] + sm.at.dec_s[hh]) * sm.at.vw_s[hh];
#pragma unroll
                    for (int off = 16; off; off >>= 1) s += __shfl_xor_sync(0xffffffffu, s, off);
                    if (lane == 0) sm.at.sc[l] = s + v_b;
                }
                __syncthreads();
                float mv = (tid < L_) ? sm.at.sc[tid] : -1e30f;
                sm.at.sred[tid] = mv; __syncthreads();
                for (int s = 128; s; s >>= 1) {
                    if (tid < s) sm.at.sred[tid] = fmaxf(sm.at.sred[tid], sm.at.sred[tid + s]);
                    __syncthreads();
                }
                float mx = sm.at.sred[0]; __syncthreads();
                float ev = (tid < L_) ? __expf(sm.at.sc[tid] - mx) : 0.f;
                sm.at.sred[tid] = ev; __syncthreads();
                for (int s = 128; s; s >>= 1) {
                    if (tid < s) sm.at.sred[tid] += sm.at.sred[tid + s];
                    __syncthreads();
                }
                float inv = 1.0f / sm.at.sred[0]; __syncthreads();
                if (tid < L_) sm.at.sc[tid] = ev * inv;
                __syncthreads();
                // ctx: warp-per-l, coalesced, 16 f-accumulators per lane
                float a[16];
#pragma unroll
                for (int i = 0; i < 16; i++) a[i] = 0.f;
                for (int l = wid; l < L_; l += 8) {
                    float s = sm.at.sc[l];
                    const float* eb = enc + ((size_t)(b * L_ + l)) * 512 + lane;
#pragma unroll
                    for (int fg = 0; fg < 16; fg++) a[fg] += s * eb[fg * 32];
                }
#pragma unroll
                for (int fg = 0; fg < 16; fg++) sm.at.red2[wid][fg * 32 + lane] = a[fg];
                __syncthreads();
                for (int f = tid; f < 512; f += 256) {
                    float a0 = 0.f;
#pragma unroll
                    for (int w = 0; w < 8; w++) a0 += sm.at.red2[w][f];
                    g_ctx[(size_t)b * 512 + f] = a0;
                }
            }
            gridbar();
        }

        // ---- gates GEMM phase: m-tile = cta>>3, K-split = cta&7 ----
        {
            float acc[2][4][4];
#pragma unroll
            for (int i = 0; i < 2; i++)
#pragma unroll
                for (int j = 0; j < 4; j++)
#pragma unroll
                    for (int r = 0; r < 4; r++) acc[i][j][r] = 0.f;

            const float* embt = g_emb + (size_t)t * B_ * 512;
            int kbeg = gm_sp * (KC_ / KS_);
            for (int k0 = kbeg; k0 < kbeg + KC_ / KS_; k0 += 32) {
#pragma unroll
                for (int i = 0; i < 2; ++i) {
                    int idx = tid + i * 256;
                    int row = idx >> 2, q = idx & 3;
                    int s = row * 40 + q * 8;
                    size_t ga = (size_t)(gm_m0 + row) * KC_ + k0 + q * 8;
                    *(uint4*)&sm.gm.As[0][s] = *(const uint4*)(g_Wc_hi + ga);
                    *(uint4*)&sm.gm.As[1][s] = *(const uint4*)(g_Wc_lo + ga);
                }
#pragma unroll
                for (int i = 0; i < 2; ++i) {
                    int idx = tid + i * 256;
                    int row = idx >> 3, q = idx & 7;
                    int kk = k0 + q * 4;
                    const float* src = (kk < 512)  ? (embt  + (size_t)row * 512 + kk)
                                     : (kk < 1024) ? (g_ctx + (size_t)row * 512 + kk - 512)
                                                   : (g_h   + (size_t)row * 512 + kk - 1024);
                    float4 v = *(const float4*)src;
                    __nv_bfloat16 hx = __float2bfloat16(v.x), hy = __float2bfloat16(v.y);
                    __nv_bfloat16 hz = __float2bfloat16(v.z), hw = __float2bfloat16(v.w);
                    int s = row * 40 + q * 4;
                    sm.gm.Bs[0][s+0]=hx; sm.gm.Bs[0][s+1]=hy;
                    sm.gm.Bs[0][s+2]=hz; sm.gm.Bs[0][s+3]=hw;
                    sm.gm.Bs[1][s+0]=__float2bfloat16(v.x - __bfloat162float(hx));
                    sm.gm.Bs[1][s+1]=__float2bfloat16(v.y - __bfloat162float(hy));
                    sm.gm.Bs[1][s+2]=__float2bfloat16(v.z - __bfloat162float(hz));
                    sm.gm.Bs[1][s+3]=__float2bfloat16(v.w - __bfloat162float(hw));
                }
                __syncthreads();
#pragma unroll
                for (int ks = 0; ks < 32; ks += 16) {
                    uint32_t ah[2][4], al[2][4], bh[4][2], bl[4][2];
#pragma unroll
                    for (int mi = 0; mi < 2; ++mi) {
                        LDMX4(ah[mi][0], ah[mi][1], ah[mi][2], ah[mi][3],
                              aAh + (uint32_t)((mi * 16 * 40 + ks) * 2));
                        LDMX4(al[mi][0], al[mi][1], al[mi][2], al[mi][3],
                              aAl + (uint32_t)((mi * 16 * 40 + ks) * 2));
                    }
                    LDMX4(bh[0][0], bh[0][1], bh[1][0], bh[1][1], aBh + (uint32_t)(ks * 2));
                    LDMX4(bh[2][0], bh[2][1], bh[3][0], bh[3][1], aBh + (uint32_t)((16 * 40 + ks) * 2));
                    LDMX4(bl[0][0], bl[0][1], bl[1][0], bl[1][1], aBl + (uint32_t)(ks * 2));
                    LDMX4(bl[2][0], bl[2][1], bl[3][0], bl[3][1], aBl + (uint32_t)((16 * 40 + ks) * 2));
#pragma unroll
                    for (int mi = 0; mi < 2; ++mi)
#pragma unroll
                        for (int ni = 0; ni < 4; ++ni) {
                            mma_bf16(acc[mi][ni], ah[mi], bh[ni]);
                            mma_bf16(acc[mi][ni], ah[mi], bl[ni]);
                            mma_bf16(acc[mi][ni], al[mi], bh[ni]);
                        }
                }
                __syncthreads();
            }

            float* base = g_gpart + (size_t)gm_sp * G4_ * 64;
            int g = lane >> 2, t4 = lane & 3;
#pragma unroll
            for (int mi = 0; mi < 2; ++mi)
#pragma unroll
                for (int rr = 0; rr < 2; ++rr) {
                    int m = gm_m0 + warp_m * 32 + mi * 16 + rr * 8 + g;
                    float* po = base + (size_t)m * 64 + warp_n * 32 + 2 * t4;
#pragma unroll
                    for (int ni = 0; ni < 4; ++ni) {
                        float2 v;
                        v.x = acc[mi][ni][rr * 2 + 0];
                        v.y = acc[mi][ni][rr * 2 + 1];
                        *(float2*)(po + ni * 8) = v;
                    }
                }
        }
        gridbar();

        // ---- pointwise phase: idx over B*H = 32768 = 128*256 ----
        {
            int idx = cta * 256 + tid;
            int b = idx & 63, h = idx >> 6;
            float gi = b_ih[h]        + b_hh[h];
            float gf = b_ih[h + 512]  + b_hh[h + 512];
            float gg = b_ih[h + 1024] + b_hh[h + 1024];
            float go = b_ih[h + 1536] + b_hh[h + 1536];
#pragma unroll
            for (int s = 0; s < KS_; ++s) {
                const float* p = g_gpart + (size_t)s * G4_ * 64;
                gi += p[(size_t)(h)        * 64 + b];
                gf += p[(size_t)(h + 512)  * 64 + b];
                gg += p[(size_t)(h + 1024) * 64 + b];
                go += p[(size_t)(h + 1536) * 64 + b];
            }
            float c  = g_c[(size_t)b * 512 + h];
            float si = 1.f / (1.f + expf(-gi));
            float sf = 1.f / (1.f + expf(-gf));
            float so = 1.f / (1.f + expf(-go));
            float c2 = sf * c + si * tanhf(gg);
            float h2 = so * tanhf(c2);
            g_c[(size_t)b * 512 + h] = c2;
            g_h[(size_t)b * 512 + h] = h2;
            size_t mrow = ((size_t)t * 64 + b) * 512 + h;
            __nv_bfloat16 hh = __float2bfloat16(h2);
            g_Hall_hi[mrow] = hh;
            g_Hall_lo[mrow] = __float2bfloat16(h2 - __bfloat162float(hh));
        }
        gridbar();
    }
}

// ---------------- launch ----------------------------------------------------
extern "C" void kernel_launch(void* const* d_in, const int* in_sizes, int n_in,
                              void* d_out, int out_size) {
    const float* enc  = (const float*)d_in[0];
    const int*   caps = (const int*)  d_in[1];
    const float* emb  = (const float*)d_in[2];
    const float* We   = (const float*)d_in[3];
    const float* be   = (const float*)d_in[4];
    const float* Wd   = (const float*)d_in[5];
    const float* bd   = (const float*)d_in[6];
    const float* vw   = (const float*)d_in[7];
    const float* vb   = (const float*)d_in[8];
    const float* W_ih = (const float*)d_in[9];
    const float* W_hh = (const float*)d_in[10];
    const float* b_ih = (const float*)d_in[11];
    const float* b_hh = (const float*)d_in[12];
    const float* Wf   = (const float*)d_in[13];
    const float* bf   = (const float*)d_in[14];
    float* out = (float*)d_out;

    cudaFuncSetAttribute(k_mma128, cudaFuncAttributeMaxDynamicSharedMemorySize, PIPE_SMEM);

    void *p_enc_hi, *p_enc_lo, *p_We_hi, *p_We_lo, *p_Wf_hi, *p_Wf_lo,
         *p_Hall_hi, *p_Hall_lo, *p_encproj;
    cudaGetSymbolAddress(&p_enc_hi, g_enc_hi);
    cudaGetSymbolAddress(&p_enc_lo, g_enc_lo);
    cudaGetSymbolAddress(&p_We_hi, g_We_hi);
    cudaGetSymbolAddress(&p_We_lo, g_We_lo);
    cudaGetSymbolAddress(&p_Wf_hi, g_Wf_hi);
    cudaGetSymbolAddress(&p_Wf_lo, g_Wf_lo);
    cudaGetSymbolAddress(&p_Hall_hi, g_Hall_hi);
    cudaGetSymbolAddress(&p_Hall_lo, g_Hall_lo);
    cudaGetSymbolAddress(&p_encproj, g_encproj);

    k_init<<<(T_ * B_ * D_) / 256, 256>>>(caps, emb);
    k_ctx0<<<(B_ * F_) / 256, 256>>>(enc);
    k_prep<<<(int)((PN0 + PN1 + PN2 + PN3) / 256), 256>>>(enc, We, Wf, W_ih, W_hh);

    // enc_proj = enc @ We^T + be
    k_mma128<<<dim3(M_ENC / 128, H_ / 128), 256, PIPE_SMEM>>>(
        (const __nv_bfloat16*)p_enc_hi, (const __nv_bfloat16*)p_enc_lo,
        (const __nv_bfloat16*)p_We_hi, (const __nv_bfloat16*)p_We_lo,
        be, (float*)p_encproj, F_, H_, 0);

    // entire 32-step recurrence in one persistent kernel
    k_loop<<<GRID_P, 256>>>(enc, Wd, bd, vw, vb, b_ih, b_hh);

    // fc logits: Hall @ Wf^T + bf
    k_mma128<<<dim3(M_FC / 128, V_ / 128), 256, PIPE_SMEM>>>(
        (const __nv_bfloat16*)p_Hall_hi, (const __nv_bfloat16*)p_Hall_lo,
        (const __nv_bfloat16*)p_Wf_hi, (const __nv_bfloat16*)p_Wf_lo,
        bf, out, H_, V_, 1);
}

// round 7
// speedup vs baseline: 2.1098x; 1.1875x over previous
#include <cuda_runtime.h>
#include <cuda_bf16.h>
#include <math.h>
#include <stdint.h>

// Problem constants
#define B_  64
#define L_  196
#define F_  512
#define T_  32
#define H_  512
#define D_  512
#define V_  32000
#define G4_ 2048
#define M_ENC (B_*L_)          // 12544
#define M_FC  (T_*B_)          // 2048
#define KC_ 1536               // D+F+H
#define GRID_P 128

// ====================== warp-mma helpers (sm_80 baseline ISA) ==============
__device__ __forceinline__ uint32_t smem_to_u32(const void* p) {
    uint32_t a;
    asm("{ .reg .u64 t; cvta.to.shared.u64 t, %1; cvt.u32.u64 %0, t; }" : "=r"(a) : "l"(p));
    return a;
}

#define LDMX4(r0,r1,r2,r3,addr) \
    asm volatile("ldmatrix.sync.aligned.m8n8.x4.shared.b16 {%0,%1,%2,%3}, [%4];" \
        : "=r"(r0),"=r"(r1),"=r"(r2),"=r"(r3) : "r"(addr))

#define CP16(dst, src) \
    asm volatile("cp.async.cg.shared.global [%0], [%1], 16;" :: "r"(dst), "l"(src))
#define CP_COMMIT() asm volatile("cp.async.commit_group;")
#define CP_WAIT(n)  asm volatile("cp.async.wait_group %0;" :: "n"(n))

__device__ __forceinline__ void mma_bf16(float* c, const uint32_t* a, const uint32_t* b) {
    asm volatile(
        "mma.sync.aligned.m16n8k16.row.col.f32.bf16.bf16.f32 "
        "{%0,%1,%2,%3}, {%4,%5,%6,%7}, {%8,%9}, {%0,%1,%2,%3};"
        : "+f"(c[0]), "+f"(c[1]), "+f"(c[2]), "+f"(c[3])
        : "r"(a[0]), "r"(a[1]), "r"(a[2]), "r"(a[3]), "r"(b[0]), "r"(b[1]));
}

__device__ __forceinline__ float ftanh(float x) {
    float y;
    asm("tanh.approx.f32 %0, %1;" : "=f"(y) : "f"(x));
    return y;
}

// ---------------- scratch (static device globals; no allocations) ----------
__device__ float g_encproj[M_ENC * H_];
__device__ float g_h[B_ * H_];
__device__ float g_c[B_ * H_];
__device__ float g_dec[B_ * H_];
__device__ float g_score[B_ * L_];
// bf16 operands
__device__ __nv_bfloat16 g_embh[T_ * B_ * D_];
__device__ __nv_bfloat16 g_embl[T_ * B_ * D_];
__device__ __nv_bfloat16 g_ctxh[B_ * F_];
__device__ __nv_bfloat16 g_ctxl[B_ * F_];
__device__ __nv_bfloat16 g_hh[B_ * H_];
__device__ __nv_bfloat16 g_hl[B_ * H_];
__device__ __nv_bfloat16 g_enc_hi[M_ENC * F_];
__device__ __nv_bfloat16 g_enc_lo[M_ENC * F_];
__device__ __nv_bfloat16 g_We_hi[H_ * F_];
__device__ __nv_bfloat16 g_We_lo[H_ * F_];
__device__ __nv_bfloat16 g_Wf_hi[(size_t)V_ * H_];
__device__ __nv_bfloat16 g_Wf_lo[(size_t)V_ * H_];
__device__ __nv_bfloat16 g_Hall_hi[M_FC * H_];
__device__ __nv_bfloat16 g_Hall_lo[M_FC * H_];
__device__ __nv_bfloat16 g_Wc_hi[(size_t)G4_ * KC_];
__device__ __nv_bfloat16 g_Wc_lo[(size_t)G4_ * KC_];
__device__ unsigned g_barArr = 0;

__device__ __forceinline__ void gridbar() {
    __syncthreads();
    if (threadIdx.x == 0) {
        unsigned my;
        asm volatile("atom.global.release.gpu.add.u32 %0, [%1], 1;"
                     : "=r"(my) : "l"(&g_barArr) : "memory");
        my += 1u;
        unsigned target = ((my + GRID_P - 1u) / GRID_P) * GRID_P;
        unsigned v;
        do {
            asm volatile("ld.global.acquire.gpu.u32 %0, [%1];"
                         : "=r"(v) : "l"(&g_barArr) : "memory");
        } while (v < target);
    }
    __syncthreads();
}

// ---------------- fused preamble splits ------------------------------------
#define PN0 (M_ENC * F_)
#define PN1 (H_ * F_)
#define PN2 ((size_t)V_ * H_)
#define PN3 ((size_t)G4_ * KC_)
__global__ void k_prep(const float* __restrict__ enc, const float* __restrict__ We,
                       const float* __restrict__ Wf, const float* __restrict__ W_ih,
                       const float* __restrict__ W_hh) {
    size_t idx = (size_t)blockIdx.x * 256 + threadIdx.x;
    float x;
    __nv_bfloat16 *hi, *lo;
    size_t off;
    if (idx < PN0) {
        off = idx; x = enc[off]; hi = g_enc_hi; lo = g_enc_lo;
    } else if (idx < PN0 + PN1) {
        off = idx - PN0; x = We[off]; hi = g_We_hi; lo = g_We_lo;
    } else if (idx < PN0 + PN1 + PN2) {
        off = idx - PN0 - PN1; x = Wf[off]; hi = g_Wf_hi; lo = g_Wf_lo;
    } else {
        off = idx - PN0 - PN1 - PN2;
        int m = (int)(off / KC_), k = (int)(off % KC_);
        x = (k < 1024) ? W_ih[(size_t)m * 1024 + k]
                       : W_hh[(size_t)m * 512 + (k - 1024)];
        hi = g_Wc_hi; lo = g_Wc_lo;
    }
    __nv_bfloat16 h = __float2bfloat16(x);
    hi[off] = h;
    lo[off] = __float2bfloat16(x - __bfloat162float(h));
}

// ---------------- init: zero state, gather embeddings -> bf16 hi/lo --------
__global__ void k_init(const int* __restrict__ captions,
                       const float* __restrict__ embedding) {
    int idx = blockIdx.x * 256 + threadIdx.x;      // T*B*D exact
    if (idx < B_ * H_) {
        g_h[idx] = 0.f; g_c[idx] = 0.f;
        g_hh[idx] = __float2bfloat16(0.f);
        g_hl[idx] = __float2bfloat16(0.f);
    }
    int t   = idx >> 15;
    int rem = idx & 32767;
    int b   = rem >> 9;
    int d   = rem & 511;
    int cap = captions[b * T_ + t];
    float x = embedding[(size_t)cap * D_ + d];
    __nv_bfloat16 h = __float2bfloat16(x);
    g_embh[idx] = h;
    g_embl[idx] = __float2bfloat16(x - __bfloat162float(h));
}

// ---------------- ctx0 = mean over L -> bf16 hi/lo -------------------------
__global__ void k_ctx0(const float* __restrict__ enc) {
    int idx = blockIdx.x * 256 + threadIdx.x;      // B*F exact
    int b = idx >> 9, f = idx & 511;
    const float* p = enc + ((size_t)b * L_) * F_ + f;
    float s = 0.f;
    for (int l = 0; l < L_; ++l) s += p[(size_t)l * F_];
    s *= (1.0f / (float)L_);
    __nv_bfloat16 h = __float2bfloat16(s);
    g_ctxh[idx] = h;
    g_ctxl[idx] = __float2bfloat16(s - __bfloat162float(h));
}

// ---------------- big GEMM (tile 128x128), pass-major mma ------------------
#define T32  (128 * 40)
#define T32B (T32 * 2)
#define PIPE_SMEM (T32B * 8)            // 81920 bytes, 2 CTA/SM

__global__ __launch_bounds__(256, 2) void k_mma128(
    const __nv_bfloat16* __restrict__ Ahi, const __nv_bfloat16* __restrict__ Alo,
    const __nv_bfloat16* __restrict__ Bhi, const __nv_bfloat16* __restrict__ Blo,
    const float* __restrict__ bias, float* __restrict__ out,
    int K, int ldc, int fc_remap)
{
    extern __shared__ char smem[];
    uint32_t sb = smem_to_u32(smem);
    int tid = threadIdx.x, wid = tid >> 5, lane = tid & 31;
    int m0 = blockIdx.x * 128, n0 = blockIdx.y * 128;
    int warp_m = wid & 1, warp_n = wid >> 1;

    float acc[4][4][4];
#pragma unroll
    for (int i = 0; i < 4; i++)
#pragma unroll
        for (int j = 0; j < 4; j++)
#pragma unroll
            for (int r = 0; r < 4; r++) acc[i][j][r] = 0.f;

    int row_ld = tid >> 1, q_ld = tid & 1;
    uint32_t so_ld = (uint32_t)(row_ld * 80 + q_ld * 32);
    int sub = lane >> 3, ri = lane & 7;
    uint32_t aoff = (uint32_t)((((sub & 1) * 8 + ri) * 40 + (sub >> 1) * 8) * 2)
                  + (uint32_t)(warp_m * 64 * 80);
    uint32_t boff = (uint32_t)((((sub >> 1) * 8 + ri) * 40 + (sub & 1) * 8) * 2)
                  + (uint32_t)(warp_n * 32 * 80);

    int NC = K >> 5;

#define ISSUE(c, s) do { \
        int k0 = (c) << 5; \
        uint32_t st = sb + (uint32_t)((s) * 4 * T32B); \
        size_t gA = (size_t)(m0 + row_ld) * K + k0 + q_ld * 16; \
        size_t gB = (size_t)(n0 + row_ld) * K + k0 + q_ld * 16; \
        CP16(st + 0 * T32B + so_ld,      Ahi + gA); \
        CP16(st + 0 * T32B + so_ld + 16, Ahi + gA + 8); \
        CP16(st + 1 * T32B + so_ld,      Alo + gA); \
        CP16(st + 1 * T32B + so_ld + 16, Alo + gA + 8); \
        CP16(st + 2 * T32B + so_ld,      Bhi + gB); \
        CP16(st + 2 * T32B + so_ld + 16, Bhi + gB + 8); \
        CP16(st + 3 * T32B + so_ld,      Blo + gB); \
        CP16(st + 3 * T32B + so_ld + 16, Blo + gB + 8); \
        CP_COMMIT(); \
    } while (0)

    ISSUE(0, 0);
    for (int c = 0; c < NC; ++c) {
        int s = c & 1;
        if (c + 1 < NC) { ISSUE(c + 1, (c + 1) & 1); CP_WAIT(1); }
        else           { CP_WAIT(0); }
        __syncthreads();
        uint32_t bAh = sb + (uint32_t)(s * 4 * T32B) + aoff;
        uint32_t bAl = bAh + T32B;
        uint32_t bBh = sb + (uint32_t)(s * 4 * T32B + 2 * T32B) + boff;
        uint32_t bBl = bBh + T32B;
#pragma unroll
        for (int ks = 0; ks < 32; ks += 16) {
            uint32_t ah[4][4], al[4][4], bh[4][2], bl[4][2];
#pragma unroll
            for (int mi = 0; mi < 4; ++mi) {
                LDMX4(ah[mi][0], ah[mi][1], ah[mi][2], ah[mi][3],
                      bAh + (uint32_t)(mi * 16 * 80 + ks * 2));
                LDMX4(al[mi][0], al[mi][1], al[mi][2], al[mi][3],
                      bAl + (uint32_t)(mi * 16 * 80 + ks * 2));
            }
            LDMX4(bh[0][0], bh[0][1], bh[1][0], bh[1][1], bBh + (uint32_t)(ks * 2));
            LDMX4(bh[2][0], bh[2][1], bh[3][0], bh[3][1], bBh + (uint32_t)(16 * 80 + ks * 2));
            LDMX4(bl[0][0], bl[0][1], bl[1][0], bl[1][1], bBl + (uint32_t)(ks * 2));
            LDMX4(bl[2][0], bl[2][1], bl[3][0], bl[3][1], bBl + (uint32_t)(16 * 80 + ks * 2));
            // pass-major ordering: each acc revisited after 16 other mmas
#pragma unroll
            for (int mi = 0; mi < 4; ++mi)
#pragma unroll
                for (int ni = 0; ni < 4; ++ni)
                    mma_bf16(acc[mi][ni], ah[mi], bh[ni]);
#pragma unroll
            for (int mi = 0; mi < 4; ++mi)
#pragma unroll
                for (int ni = 0; ni < 4; ++ni)
                    mma_bf16(acc[mi][ni], ah[mi], bl[ni]);
#pragma unroll
            for (int mi = 0; mi < 4; ++mi)
#pragma unroll
                for (int ni = 0; ni < 4; ++ni)
                    mma_bf16(acc[mi][ni], al[mi], bh[ni]);
        }
        __syncthreads();
    }
#undef ISSUE

    int g = lane >> 2, t4 = lane & 3;
    float2 bv[4];
#pragma unroll
    for (int ni = 0; ni < 4; ++ni)
        bv[ni] = *(const float2*)(bias + n0 + warp_n * 32 + ni * 8 + 2 * t4);
#pragma unroll
    for (int mi = 0; mi < 4; ++mi)
#pragma unroll
        for (int rr = 0; rr < 2; ++rr) {
            int m = m0 + warp_m * 64 + mi * 16 + rr * 8 + g;
            int row = fc_remap ? ((m & 63) * T_ + (m >> 6)) : m;
            float* po = out + (size_t)row * ldc + n0 + warp_n * 32 + 2 * t4;
#pragma unroll
            for (int ni = 0; ni < 4; ++ni) {
                float2 v;
                v.x = acc[mi][ni][rr * 2 + 0] + bv[ni].x;
                v.y = acc[mi][ni][rr * 2 + 1] + bv[ni].y;
                *(float2*)(po + ni * 8) = v;
            }
        }
}

// ---------------- persistent fused recurrence kernel ------------------------
// dyn smem layout (bytes):
//   gates: stage s at s*23040: Ah[16x72]@0, Al@2304, Bh[64x72]@4608, Bl@13824
//          gatebuf @46080: 2 x [16][64] fp32 (8192)   -> max 54272
//   dec:   hs [64][65] f32 @0 (16640), ws [4][64] @16640
//   scores: dec_s[512]@0, vw_s[512]@2048
//   ctx:   sc[200]@0, sred[256]@800+pad->@1024, red2[8][256]@2048
#define LOOP_SMEM 55296

__global__ __launch_bounds__(256, 1) void k_loop(
    const float* __restrict__ enc, const float* __restrict__ Wd,
    const float* __restrict__ bd, const float* __restrict__ vw,
    const float* __restrict__ vb, const float* __restrict__ b_ih,
    const float* __restrict__ b_hh)
{
    extern __shared__ char smL[];
    uint32_t sb = smem_to_u32(smL);
    int cta = blockIdx.x;
    int tid = threadIdx.x, wid = tid >> 5, lane = tid & 31;
    int sub = lane >> 3, ri = lane & 7;

    // fused-gates constants
    int khalf = wid >> 2, ng = wid & 3;     // K-half within chunk, batch group
    uint32_t aoffG = (uint32_t)((((sub & 1) * 8 + ri) * 72 + (sub >> 1) * 8) * 2);
    uint32_t boffG = (uint32_t)((((sub >> 1) * 8 + ri) * 72 + (sub & 1) * 8) * 2)
                   + (uint32_t)(ng * 16 * 144);

    for (int t = 0; t < T_; ++t) {
        if (t > 0) {
            // ---- dec: cta computes dec[:, cta*4 .. +3] ----
            {
                float* hs = (float*)smL;                // [64][65]
                float* ws = (float*)(smL + 16640);      // [4][64]
                int n0 = cta * 4;
                int bq = tid & 63, jj = tid >> 6;
                float acc = 0.f;
                for (int kb = 0; kb < 512; kb += 64) {
#pragma unroll
                    for (int it = 0; it < 4; ++it) {
                        int r = (tid >> 4) + it * 16;
                        int kk = (tid & 15) * 4;
                        float4 v = *(const float4*)(g_h + (size_t)r * 512 + kb + kk);
                        hs[r * 65 + kk + 0] = v.x; hs[r * 65 + kk + 1] = v.y;
                        hs[r * 65 + kk + 2] = v.z; hs[r * 65 + kk + 3] = v.w;
                    }
                    if (tid < 64) {
                        int n = tid >> 4, kk = (tid & 15) * 4;
                        float4 v = *(const float4*)(Wd + (size_t)(n0 + n) * 512 + kb + kk);
                        ws[n * 64 + kk + 0] = v.x; ws[n * 64 + kk + 1] = v.y;
                        ws[n * 64 + kk + 2] = v.z; ws[n * 64 + kk + 3] = v.w;
                    }
                    __syncthreads();
#pragma unroll
                    for (int k = 0; k < 64; ++k)
                        acc += hs[bq * 65 + k] * ws[jj * 64 + k];
                    __syncthreads();
                }
                g_dec[(size_t)bq * 512 + n0 + jj] = acc + bd[n0 + jj];
            }
            gridbar();

            // ---- scores: 128 CTAs, b = cta>>1, half-l each ----
            {
                float* dec_s = (float*)smL;
                float* vw_s  = (float*)(smL + 2048);
                int b = cta >> 1, half = cta & 1;
                for (int i = tid; i < 512; i += 256) {
                    dec_s[i] = g_dec[(size_t)b * 512 + i];
                    vw_s[i]  = vw[i];
                }
                __syncthreads();
                float v_b = vb[0];
                int lbase = half * 98;
                for (int l = lbase + wid; l < lbase + 98; l += 8) {
                    const float* ep = g_encproj + ((size_t)(b * L_ + l)) * 512;
                    float s = 0.f;
                    for (int hh = lane; hh < 512; hh += 32)
                        s += ftanh(ep[hh] + dec_s[hh]) * vw_s[hh];
#pragma unroll
                    for (int off = 16; off; off >>= 1) s += __shfl_xor_sync(0xffffffffu, s, off);
                    if (lane == 0) g_score[b * L_ + l] = s + v_b;
                }
            }
            gridbar();

            // ---- softmax(local) + ctx: 128 CTAs, b = cta>>1, 256 f each ----
            {
                float* sc   = (float*)smL;              // [200]
                float* sred = (float*)(smL + 1024);     // [256]
                float* red2 = (float*)(smL + 2048);     // [8][256]
                int b = cta >> 1, f0 = (cta & 1) * 256;
                float mv = (tid < L_) ? g_score[b * L_ + tid] : -1e30f;
                if (tid < L_) sc[tid] = mv;
                sred[tid] = mv; __syncthreads();
                for (int s = 128; s; s >>= 1) {
                    if (tid < s) sred[tid] = fmaxf(sred[tid], sred[tid + s]);
                    __syncthreads();
                }
                float mx = sred[0]; __syncthreads();
                float ev = (tid < L_) ? __expf(sc[tid] - mx) : 0.f;
                sred[tid] = ev; __syncthreads();
                for (int s = 128; s; s >>= 1) {
                    if (tid < s) sred[tid] += sred[tid + s];
                    __syncthreads();
                }
                float inv = 1.0f / sred[0]; __syncthreads();
                if (tid < L_) sc[tid] = ev * inv;
                __syncthreads();
                float a[8];
#pragma unroll
                for (int i = 0; i < 8; i++) a[i] = 0.f;
                for (int l = wid; l < L_; l += 8) {
                    float s = sc[l];
                    const float* eb = enc + ((size_t)(b * L_ + l)) * 512 + f0 + lane;
#pragma unroll
                    for (int fg = 0; fg < 8; fg++) a[fg] += s * eb[fg * 32];
                }
#pragma unroll
                for (int fg = 0; fg < 8; fg++) red2[wid * 256 + fg * 32 + lane] = a[fg];
                __syncthreads();
                {
                    float a0 = 0.f;
#pragma unroll
                    for (int w = 0; w < 8; w++) a0 += red2[w * 256 + tid];
                    int fi = b * 512 + f0 + tid;
                    __nv_bfloat16 h = __float2bfloat16(a0);
                    g_ctxh[fi] = h;
                    g_ctxl[fi] = __float2bfloat16(a0 - __bfloat162float(h));
                }
            }
            gridbar();
        }

        // ---- fused gates GEMM + pointwise ----
        {
            const __nv_bfloat16* embt_h = g_embh + (size_t)t * B_ * 512;
            const __nv_bfloat16* embt_l = g_embl + (size_t)t * B_ * 512;
            float accs[3][2][4];
#pragma unroll
            for (int p = 0; p < 3; p++)
#pragma unroll
                for (int n = 0; n < 2; n++)
#pragma unroll
                    for (int r = 0; r < 4; r++) accs[p][n][r] = 0.f;

#define GISSUE(c, s) do { \
        int k0 = (c) * 64; \
        int region = k0 >> 9; \
        int kb = k0 - (region << 9); \
        const __nv_bfloat16* srcH = (region == 0) ? embt_h : (region == 1) ? g_ctxh : g_hh; \
        const __nv_bfloat16* srcL = (region == 0) ? embt_l : (region == 1) ? g_ctxl : g_hl; \
        uint32_t st = sb + (uint32_t)((s) * 23040); \
        if (tid < 128) { \
            int sr = tid >> 3, q = tid & 7; \
            int gg_ = sr >> 2, rr_ = sr & 3; \
            size_t ga = (size_t)(gg_ * 512 + cta * 4 + rr_) * KC_ + k0 + q * 8; \
            CP16(st + sr * 144 + q * 16, g_Wc_hi + ga); \
        } else { \
            int t2 = tid - 128; int sr = t2 >> 3, q = t2 & 7; \
            int gg_ = sr >> 2, rr_ = sr & 3; \
            size_t ga = (size_t)(gg_ * 512 + cta * 4 + rr_) * KC_ + k0 + q * 8; \
            CP16(st + 2304 + sr * 144 + q * 16, g_Wc_lo + ga); \
        } \
        _Pragma("unroll") \
        for (int uu = 0; uu < 2; ++uu) { \
            int u = tid * 2 + uu; int row = u >> 3, q = u & 7; \
            CP16(st + 4608 + row * 144 + q * 16, srcH + (size_t)row * 512 + kb + q * 8); \
            CP16(st + 13824 + row * 144 + q * 16, srcL + (size_t)row * 512 + kb + q * 8); \
        } \
        CP_COMMIT(); \
    } while (0)

            GISSUE(0, 0);
            for (int c = 0; c < 24; ++c) {
                int s = c & 1;
                if (c + 1 < 24) { GISSUE(c + 1, (c + 1) & 1); CP_WAIT(1); }
                else            { CP_WAIT(0); }
                __syncthreads();
                uint32_t st = sb + (uint32_t)(s * 23040);
#pragma unroll
                for (int ks2 = 0; ks2 < 2; ++ks2) {
                    int ks = khalf * 32 + ks2 * 16;
                    uint32_t ah[4], al[4], bh[2][2], bl[2][2];
                    LDMX4(ah[0], ah[1], ah[2], ah[3], st + aoffG + (uint32_t)(ks * 2));
                    LDMX4(al[0], al[1], al[2], al[3], st + 2304 + aoffG + (uint32_t)(ks * 2));
                    LDMX4(bh[0][0], bh[0][1], bh[1][0], bh[1][1],
                          st + 4608 + boffG + (uint32_t)(ks * 2));
                    LDMX4(bl[0][0], bl[0][1], bl[1][0], bl[1][1],
                          st + 13824 + boffG + (uint32_t)(ks * 2));
#pragma unroll
                    for (int ni = 0; ni < 2; ++ni) mma_bf16(accs[0][ni], ah, bh[ni]);
#pragma unroll
                    for (int ni = 0; ni < 2; ++ni) mma_bf16(accs[1][ni], ah, bl[ni]);
#pragma unroll
                    for (int ni = 0; ni < 2; ++ni) mma_bf16(accs[2][ni], al, bh[ni]);
                }
                __syncthreads();
            }
#undef GISSUE

            // store gate partials (two K-half buffers)
            float* gbuf = (float*)(smL + 46080) + khalf * 1024;  // [16][64]
            int g4 = lane >> 2, t4 = lane & 3;
#pragma unroll
            for (int ni = 0; ni < 2; ++ni) {
                int coln = ng * 16 + ni * 8 + 2 * t4;
                float c0 = accs[0][ni][0] + accs[1][ni][0] + accs[2][ni][0];
                float c1 = accs[0][ni][1] + accs[1][ni][1] + accs[2][ni][1];
                float c2 = accs[0][ni][2] + accs[1][ni][2] + accs[2][ni][2];
                float c3 = accs[0][ni][3] + accs[1][ni][3] + accs[2][ni][3];
                gbuf[g4 * 64 + coln]           = c0;
                gbuf[g4 * 64 + coln + 1]       = c1;
                gbuf[(g4 + 8) * 64 + coln]     = c2;
                gbuf[(g4 + 8) * 64 + coln + 1] = c3;
            }
            __syncthreads();

            // pointwise: thread owns (h = cta*4 + r, batch bb)
            {
                float* gb0 = (float*)(smL + 46080);
                float* gb1 = gb0 + 1024;
                int r = tid >> 6, bb = tid & 63;
                int h = cta * 4 + r;
                float gi = gb0[r * 64 + bb]        + gb1[r * 64 + bb]
                         + b_ih[h] + b_hh[h];
                float gf = gb0[(4 + r) * 64 + bb]  + gb1[(4 + r) * 64 + bb]
                         + b_ih[512 + h] + b_hh[512 + h];
                float gg = gb0[(8 + r) * 64 + bb]  + gb1[(8 + r) * 64 + bb]
                         + b_ih[1024 + h] + b_hh[1024 + h];
                float go = gb0[(12 + r) * 64 + bb] + gb1[(12 + r) * 64 + bb]
                         + b_ih[1536 + h] + b_hh[1536 + h];
                float c  = g_c[(size_t)bb * 512 + h];
                float si = 1.f / (1.f + __expf(-gi));
                float sf = 1.f / (1.f + __expf(-gf));
                float so = 1.f / (1.f + __expf(-go));
                float eg = __expf(2.f * gg);
                float tg = 1.f - 2.f / (eg + 1.f);
                float c2 = sf * c + si * tg;
                float ec = __expf(2.f * c2);
                float tc = 1.f - 2.f / (ec + 1.f);
                float h2 = so * tc;
                g_c[(size_t)bb * 512 + h] = c2;
                g_h[(size_t)bb * 512 + h] = h2;
                __nv_bfloat16 hh = __float2bfloat16(h2);
                __nv_bfloat16 hl = __float2bfloat16(h2 - __bfloat162float(hh));
                g_hh[(size_t)bb * 512 + h] = hh;
                g_hl[(size_t)bb * 512 + h] = hl;
                size_t mrow = ((size_t)t * 64 + bb) * 512 + h;
                g_Hall_hi[mrow] = hh;
                g_Hall_lo[mrow] = hl;
            }
        }
        gridbar();
    }
}

// ---------------- launch ----------------------------------------------------
extern "C" void kernel_launch(void* const* d_in, const int* in_sizes, int n_in,
                              void* d_out, int out_size) {
    const float* enc  = (const float*)d_in[0];
    const int*   caps = (const int*)  d_in[1];
    const float* emb  = (const float*)d_in[2];
    const float* We   = (const float*)d_in[3];
    const float* be   = (const float*)d_in[4];
    const float* Wd   = (const float*)d_in[5];
    const float* bd   = (const float*)d_in[6];
    const float* vw   = (const float*)d_in[7];
    const float* vb   = (const float*)d_in[8];
    const float* W_ih = (const float*)d_in[9];
    const float* W_hh = (const float*)d_in[10];
    const float* b_ih = (const float*)d_in[11];
    const float* b_hh = (const float*)d_in[12];
    const float* Wf   = (const float*)d_in[13];
    const float* bf   = (const float*)d_in[14];
    float* out = (float*)d_out;

    cudaFuncSetAttribute(k_mma128, cudaFuncAttributeMaxDynamicSharedMemorySize, PIPE_SMEM);
    cudaFuncSetAttribute(k_loop, cudaFuncAttributeMaxDynamicSharedMemorySize, LOOP_SMEM);

    void *p_enc_hi, *p_enc_lo, *p_We_hi, *p_We_lo, *p_Wf_hi, *p_Wf_lo,
         *p_Hall_hi, *p_Hall_lo, *p_encproj;
    cudaGetSymbolAddress(&p_enc_hi, g_enc_hi);
    cudaGetSymbolAddress(&p_enc_lo, g_enc_lo);
    cudaGetSymbolAddress(&p_We_hi, g_We_hi);
    cudaGetSymbolAddress(&p_We_lo, g_We_lo);
    cudaGetSymbolAddress(&p_Wf_hi, g_Wf_hi);
    cudaGetSymbolAddress(&p_Wf_lo, g_Wf_lo);
    cudaGetSymbolAddress(&p_Hall_hi, g_Hall_hi);
    cudaGetSymbolAddress(&p_Hall_lo, g_Hall_lo);
    cudaGetSymbolAddress(&p_encproj, g_encproj);

    k_init<<<(T_ * B_ * D_) / 256, 256>>>(caps, emb);
    k_ctx0<<<(B_ * F_) / 256, 256>>>(enc);
    k_prep<<<(int)((PN0 + PN1 + PN2 + PN3) / 256), 256>>>(enc, We, Wf, W_ih, W_hh);

    // enc_proj = enc @ We^T + be
    k_mma128<<<dim3(M_ENC / 128, H_ / 128), 256, PIPE_SMEM>>>(
        (const __nv_bfloat16*)p_enc_hi, (const __nv_bfloat16*)p_enc_lo,
        (const __nv_bfloat16*)p_We_hi, (const __nv_bfloat16*)p_We_lo,
        be, (float*)p_encproj, F_, H_, 0);

    // entire 32-step recurrence in one persistent kernel
    k_loop<<<GRID_P, 256, LOOP_SMEM>>>(enc, Wd, bd, vw, vb, b_ih, b_hh);

    // fc logits: Hall @ Wf^T + bf
    k_mma128<<<dim3(M_FC / 128, V_ / 128), 256, PIPE_SMEM>>>(
        (const __nv_bfloat16*)p_Hall_hi, (const __nv_bfloat16*)p_Hall_lo,
        (const __nv_bfloat16*)p_Wf_hi, (const __nv_bfloat16*)p_Wf_lo,
        bf, out, H_, V_, 1);
}